// round 1
// baseline (speedup 1.0000x reference)
#include <cuda_runtime.h>
#include <math.h>

#define TT 4096
#define HH 1536
#define II 768
#define EE 64
#define KK 8
#define CC 1024

// Scratch: device globals (no allocation allowed).
__device__ int   g_cnt[EE];
__device__ int   g_rowtok[EE * CC];
__device__ float g_roww[EE * CC];
__device__ float g_h[(size_t)EE * CC * II];   // gathered SwiGLU activations [E, C, I]

__global__ void zero_cnt_kernel() {
    if (threadIdx.x < EE) g_cnt[threadIdx.x] = 0;
}

__global__ void zero_out_kernel(float4* out) {
    int i = blockIdx.x * blockDim.x + threadIdx.x;
    out[i] = make_float4(0.f, 0.f, 0.f, 0.f);
}

// ---------------------------------------------------------------------------
// Router: logits = x @ gate_w^T, sigmoid, +bias for selection, top-8,
// weights = raw scores renormalized. Dispatch via atomic per-expert counters.
// 16 tokens per block, 256 threads, grid = T/16.
// ---------------------------------------------------------------------------
__global__ __launch_bounds__(256) void router_kernel(
    const float* __restrict__ x,
    const float* __restrict__ gw,
    const float* __restrict__ bias)
{
    __shared__ float xs[16][65];
    __shared__ float gs[64][65];
    __shared__ float s_sel[16][64];
    __shared__ float s_sc[16][64];

    int tid  = threadIdx.x;
    int tok0 = blockIdx.x * 16;
    int t    = tid >> 4;    // 0..15 token within block
    int eg   = tid & 15;    // expert group

    float acc[4] = {0.f, 0.f, 0.f, 0.f};

    for (int c = 0; c < HH / 64; c++) {
        int h0 = c * 64;
        __syncthreads();
        // load x tile [16][64]
        {
            int r = tid >> 4, hq = (tid & 15) << 2;
            float4 v = *(const float4*)(x + (size_t)(tok0 + r) * HH + h0 + hq);
            xs[r][hq] = v.x; xs[r][hq + 1] = v.y; xs[r][hq + 2] = v.z; xs[r][hq + 3] = v.w;
        }
        // load gate tile [64][64]
        #pragma unroll
        for (int r4 = 0; r4 < 4; r4++) {
            int idx = tid + r4 * 256;
            int e2 = idx >> 4, hq = (idx & 15) << 2;
            float4 v = *(const float4*)(gw + (size_t)e2 * HH + h0 + hq);
            gs[e2][hq] = v.x; gs[e2][hq + 1] = v.y; gs[e2][hq + 2] = v.z; gs[e2][hq + 3] = v.w;
        }
        __syncthreads();
        #pragma unroll 8
        for (int h = 0; h < 64; h++) {
            float xv = xs[t][h];
            #pragma unroll
            for (int j = 0; j < 4; j++)
                acc[j] = fmaf(xv, gs[eg + 16 * j][h], acc[j]);
        }
    }

    #pragma unroll
    for (int j = 0; j < 4; j++) {
        int e = eg + 16 * j;
        float sc = 1.f / (1.f + expf(-acc[j]));
        s_sc[t][e]  = sc;
        s_sel[t][e] = sc + bias[e];
    }
    __syncthreads();

    // top-8 per token: each warp handles 2 tokens
    int warp = tid >> 5, lane = tid & 31;
    for (int tt = warp; tt < 16; tt += 8) {
        float v0 = s_sel[tt][lane];
        float v1 = s_sel[tt][lane + 32];
        int bid[KK];
        float wsum = 0.f;
        #pragma unroll
        for (int k = 0; k < KK; k++) {
            float v; int id;
            if (v0 >= v1) { v = v0; id = lane; } else { v = v1; id = lane + 32; }
            #pragma unroll
            for (int off = 16; off; off >>= 1) {
                float ov = __shfl_xor_sync(0xffffffffu, v, off);
                int   oi = __shfl_xor_sync(0xffffffffu, id, off);
                if (ov > v || (ov == v && oi < id)) { v = ov; id = oi; }
            }
            bid[k] = id;
            wsum += s_sc[tt][id];
            if (id == lane)      v0 = -1e30f;
            if (id == lane + 32) v1 = -1e30f;
        }
        if (lane < KK) {
            int e = bid[lane];
            float wgt = s_sc[tt][e] / wsum;
            int pos = atomicAdd(&g_cnt[e], 1);
            if (pos < CC) {
                g_rowtok[e * CC + pos] = tok0 + tt;
                g_roww[e * CC + pos]   = wgt;
            }
        }
    }
}

// ---------------------------------------------------------------------------
// GEMM1: per expert, gathered A rows (tokens) x (w_gate, w_up), fused
// SiLU(g)*u epilogue -> g_h.  BM=BN=64, BK=16, 256 threads, 4x4 per thread
// for each of the two output matrices.
// ---------------------------------------------------------------------------
__global__ __launch_bounds__(256) void gemm1_kernel(
    const float* __restrict__ x,
    const float* __restrict__ wg,
    const float* __restrict__ wu)
{
    int e   = blockIdx.z;
    int cnt = min(g_cnt[e], CC);
    int m0  = blockIdx.y * 64;
    if (m0 >= cnt) return;
    int n0  = blockIdx.x * 64;

    __shared__ float As[16][64];
    __shared__ float Bg[16][64];
    __shared__ float Bu[16][64];

    int tid  = threadIdx.x;
    int lrow = tid >> 2;          // 0..63
    int lkq  = (tid & 3) << 2;    // 0,4,8,12

    int tok = -1;
    if (m0 + lrow < cnt) tok = g_rowtok[e * CC + m0 + lrow];
    const float* ap  = x + (size_t)max(tok, 0) * HH + lkq;
    const float* bgp = wg + ((size_t)e * II + n0 + lrow) * HH + lkq;
    const float* bup = wu + ((size_t)e * II + n0 + lrow) * HH + lkq;

    int tx = (tid & 15) << 2;
    int ty = (tid >> 4) << 2;

    float ag[4][4] = {}, au[4][4] = {};

    for (int k0 = 0; k0 < HH; k0 += 16) {
        float4 av = (tok >= 0) ? *(const float4*)(ap + k0) : make_float4(0, 0, 0, 0);
        float4 gv = *(const float4*)(bgp + k0);
        float4 uv = *(const float4*)(bup + k0);
        __syncthreads();
        As[lkq][lrow] = av.x; As[lkq + 1][lrow] = av.y; As[lkq + 2][lrow] = av.z; As[lkq + 3][lrow] = av.w;
        Bg[lkq][lrow] = gv.x; Bg[lkq + 1][lrow] = gv.y; Bg[lkq + 2][lrow] = gv.z; Bg[lkq + 3][lrow] = gv.w;
        Bu[lkq][lrow] = uv.x; Bu[lkq + 1][lrow] = uv.y; Bu[lkq + 2][lrow] = uv.z; Bu[lkq + 3][lrow] = uv.w;
        __syncthreads();
        #pragma unroll
        for (int k = 0; k < 16; k++) {
            float4 a  = *(const float4*)&As[k][ty];
            float4 bg = *(const float4*)&Bg[k][tx];
            float4 bu = *(const float4*)&Bu[k][tx];
            float aa[4]  = {a.x, a.y, a.z, a.w};
            float bga[4] = {bg.x, bg.y, bg.z, bg.w};
            float bua[4] = {bu.x, bu.y, bu.z, bu.w};
            #pragma unroll
            for (int i = 0; i < 4; i++)
                #pragma unroll
                for (int j = 0; j < 4; j++) {
                    ag[i][j] = fmaf(aa[i], bga[j], ag[i][j]);
                    au[i][j] = fmaf(aa[i], bua[j], au[i][j]);
                }
        }
    }

    #pragma unroll
    for (int i = 0; i < 4; i++) {
        int m = m0 + ty + i;
        if (m < cnt) {
            float r[4];
            #pragma unroll
            for (int j = 0; j < 4; j++) {
                float g = ag[i][j];
                float s = 1.f / (1.f + expf(-g));
                r[j] = g * s * au[i][j];
            }
            *(float4*)&g_h[((size_t)e * CC + m) * II + n0 + tx] =
                make_float4(r[0], r[1], r[2], r[3]);
        }
    }
}

// ---------------------------------------------------------------------------
// GEMM2: y = h @ w_down^T per expert, weighted scatter-add into out.
// ---------------------------------------------------------------------------
__global__ __launch_bounds__(256) void gemm2_kernel(
    const float* __restrict__ wd,
    float* __restrict__ out)
{
    int e   = blockIdx.z;
    int cnt = min(g_cnt[e], CC);
    int m0  = blockIdx.y * 64;
    if (m0 >= cnt) return;
    int n0  = blockIdx.x * 64;

    __shared__ float As[16][64];
    __shared__ float Bs[16][64];

    int tid  = threadIdx.x;
    int lrow = tid >> 2;
    int lkq  = (tid & 3) << 2;

    bool arow_ok = (m0 + lrow) < cnt;
    const float* ap = &g_h[((size_t)e * CC + m0 + lrow) * II + lkq];
    const float* bp = wd + ((size_t)e * HH + n0 + lrow) * II + lkq;

    int tx = (tid & 15) << 2;
    int ty = (tid >> 4) << 2;

    float acc[4][4] = {};

    for (int k0 = 0; k0 < II; k0 += 16) {
        float4 av = arow_ok ? *(const float4*)(ap + k0) : make_float4(0, 0, 0, 0);
        float4 bv = *(const float4*)(bp + k0);
        __syncthreads();
        As[lkq][lrow] = av.x; As[lkq + 1][lrow] = av.y; As[lkq + 2][lrow] = av.z; As[lkq + 3][lrow] = av.w;
        Bs[lkq][lrow] = bv.x; Bs[lkq + 1][lrow] = bv.y; Bs[lkq + 2][lrow] = bv.z; Bs[lkq + 3][lrow] = bv.w;
        __syncthreads();
        #pragma unroll
        for (int k = 0; k < 16; k++) {
            float4 a = *(const float4*)&As[k][ty];
            float4 b = *(const float4*)&Bs[k][tx];
            float aa[4] = {a.x, a.y, a.z, a.w};
            float bb[4] = {b.x, b.y, b.z, b.w};
            #pragma unroll
            for (int i = 0; i < 4; i++)
                #pragma unroll
                for (int j = 0; j < 4; j++)
                    acc[i][j] = fmaf(aa[i], bb[j], acc[i][j]);
        }
    }

    #pragma unroll
    for (int i = 0; i < 4; i++) {
        int m = m0 + ty + i;
        if (m < cnt) {
            int   tok = g_rowtok[e * CC + m];
            float w   = g_roww[e * CC + m];
            float* op = out + (size_t)tok * HH + n0 + tx;
            #pragma unroll
            for (int j = 0; j < 4; j++)
                atomicAdd(op + j, w * acc[i][j]);
        }
    }
}

// ---------------------------------------------------------------------------
extern "C" void kernel_launch(void* const* d_in, const int* in_sizes, int n_in,
                              void* d_out, int out_size)
{
    const float* x      = (const float*)d_in[0];
    const float* gw     = (const float*)d_in[1];
    const float* bias   = (const float*)d_in[2];
    const float* w_gate = (const float*)d_in[3];
    const float* w_up   = (const float*)d_in[4];
    const float* w_down = (const float*)d_in[5];
    float* out = (float*)d_out;

    zero_cnt_kernel<<<1, 64>>>();
    zero_out_kernel<<<(TT * HH / 4) / 256, 256>>>((float4*)out);
    router_kernel<<<TT / 16, 256>>>(x, gw, bias);
    gemm1_kernel<<<dim3(II / 64, CC / 64, EE), 256>>>(x, w_gate, w_up);
    gemm2_kernel<<<dim3(HH / 64, CC / 64, EE), 256>>>(w_down, out);
}

// round 2
// speedup vs baseline: 3.5518x; 3.5518x over previous
#include <cuda_runtime.h>
#include <math.h>

#define TT 4096
#define HH 1536
#define II 768
#define EE 64
#define KK 8
#define CC 1024
#define AS 20   // smem row stride in floats (bank-conflict-free for frag loads)

// Scratch (no allocation allowed).
__device__ int   g_cnt[EE];
__device__ int   g_rowtok[EE * CC];
__device__ float g_roww[EE * CC];
__device__ float g_h[(size_t)EE * CC * II];   // SwiGLU activations [E, C, I]

// ---------------------------------------------------------------------------
// helpers
// ---------------------------------------------------------------------------
__device__ __forceinline__ unsigned f2tf(float f) {
    unsigned r; asm("cvt.rna.tf32.f32 %0, %1;" : "=r"(r) : "f"(f)); return r;
}
__device__ __forceinline__ void mma8(float* c, const unsigned* a, unsigned b0, unsigned b1) {
    asm volatile(
        "mma.sync.aligned.m16n8k8.row.col.f32.tf32.tf32.f32 "
        "{%0,%1,%2,%3}, {%4,%5,%6,%7}, {%8,%9}, {%0,%1,%2,%3};\n"
        : "+f"(c[0]), "+f"(c[1]), "+f"(c[2]), "+f"(c[3])
        : "r"(a[0]), "r"(a[1]), "r"(a[2]), "r"(a[3]), "r"(b0), "r"(b1));
}
__device__ __forceinline__ void cpa(unsigned dst, const void* src, unsigned sz) {
    asm volatile("cp.async.cg.shared.global [%0], [%1], 16, %2;\n"
                 :: "r"(dst), "l"(src), "r"(sz));
}
#define CP_COMMIT asm volatile("cp.async.commit_group;\n")
#define CP_WAIT1  asm volatile("cp.async.wait_group 1;\n")
#define CP_WAIT0  asm volatile("cp.async.wait_group 0;\n")

__global__ void zero_cnt_kernel() {
    if (threadIdx.x < EE) g_cnt[threadIdx.x] = 0;
}
__global__ void zero_out_kernel(float4* out) {
    int i = blockIdx.x * blockDim.x + threadIdx.x;
    out[i] = make_float4(0.f, 0.f, 0.f, 0.f);
}

// ---------------------------------------------------------------------------
// Router: exact fp32 (top-k selection is tie-sensitive; keep full precision).
// ---------------------------------------------------------------------------
__global__ __launch_bounds__(256) void router_kernel(
    const float* __restrict__ x,
    const float* __restrict__ gw,
    const float* __restrict__ bias)
{
    __shared__ float xs[16][65];
    __shared__ float gs[64][65];
    __shared__ float s_sel[16][64];
    __shared__ float s_sc[16][64];

    int tid  = threadIdx.x;
    int tok0 = blockIdx.x * 16;
    int t    = tid >> 4;
    int eg   = tid & 15;

    float acc[4] = {0.f, 0.f, 0.f, 0.f};

    for (int c = 0; c < HH / 64; c++) {
        int h0 = c * 64;
        __syncthreads();
        {
            int r = tid >> 4, hq = (tid & 15) << 2;
            float4 v = *(const float4*)(x + (size_t)(tok0 + r) * HH + h0 + hq);
            xs[r][hq] = v.x; xs[r][hq + 1] = v.y; xs[r][hq + 2] = v.z; xs[r][hq + 3] = v.w;
        }
        #pragma unroll
        for (int r4 = 0; r4 < 4; r4++) {
            int idx = tid + r4 * 256;
            int e2 = idx >> 4, hq = (idx & 15) << 2;
            float4 v = *(const float4*)(gw + (size_t)e2 * HH + h0 + hq);
            gs[e2][hq] = v.x; gs[e2][hq + 1] = v.y; gs[e2][hq + 2] = v.z; gs[e2][hq + 3] = v.w;
        }
        __syncthreads();
        #pragma unroll 8
        for (int h = 0; h < 64; h++) {
            float xv = xs[t][h];
            #pragma unroll
            for (int j = 0; j < 4; j++)
                acc[j] = fmaf(xv, gs[eg + 16 * j][h], acc[j]);
        }
    }

    #pragma unroll
    for (int j = 0; j < 4; j++) {
        int e = eg + 16 * j;
        float sc = 1.f / (1.f + expf(-acc[j]));
        s_sc[t][e]  = sc;
        s_sel[t][e] = sc + bias[e];
    }
    __syncthreads();

    int warp = tid >> 5, lane = tid & 31;
    for (int tt = warp; tt < 16; tt += 8) {
        float v0 = s_sel[tt][lane];
        float v1 = s_sel[tt][lane + 32];
        int bid[KK];
        float wsum = 0.f;
        #pragma unroll
        for (int k = 0; k < KK; k++) {
            float v; int id;
            if (v0 >= v1) { v = v0; id = lane; } else { v = v1; id = lane + 32; }
            #pragma unroll
            for (int off = 16; off; off >>= 1) {
                float ov = __shfl_xor_sync(0xffffffffu, v, off);
                int   oi = __shfl_xor_sync(0xffffffffu, id, off);
                if (ov > v || (ov == v && oi < id)) { v = ov; id = oi; }
            }
            bid[k] = id;
            wsum += s_sc[tt][id];
            if (id == lane)      v0 = -1e30f;
            if (id == lane + 32) v1 = -1e30f;
        }
        if (lane < KK) {
            int e = bid[lane];
            float wgt = s_sc[tt][e] / wsum;
            int pos = atomicAdd(&g_cnt[e], 1);
            if (pos < CC) {
                g_rowtok[e * CC + pos] = tok0 + tt;
                g_roww[e * CC + pos]   = wgt;
            }
        }
    }
}

// ---------------------------------------------------------------------------
// GEMM1 (tf32 tensor core): gathered A[128 x H] x {w_gate, w_up}[64 x H]^T
// fused SiLU(g)*u -> g_h.  BM=128, BN=64(+64 up), 8 warps (4m x 2n),
// warp tile 32 x (32g + 32u), 2-stage cp.async pipeline, BK=16.
// ---------------------------------------------------------------------------
__global__ __launch_bounds__(256) void gemm1_kernel(
    const float* __restrict__ x,
    const float* __restrict__ wg,
    const float* __restrict__ wu)
{
    int e   = blockIdx.z;
    int cnt = min(g_cnt[e], CC);
    int m0  = blockIdx.y * 128;
    if (m0 >= cnt) return;
    int n0  = blockIdx.x * 64;

    __shared__ float As_[2][128 * AS];
    __shared__ float Bg_[2][64 * AS];
    __shared__ float Bu_[2][64 * AS];

    int tid = threadIdx.x;

    // cp.async source setup (A: 2 chunks/thread, gathered rows; zfill past cnt)
    const float* aptr[2]; unsigned asz[2]; unsigned aoff[2];
    #pragma unroll
    for (int i = 0; i < 2; i++) {
        int chunk = tid + i * 256;
        int r = chunk >> 2, kq = (chunk & 3) * 4;
        int m = m0 + r;
        int ok = m < cnt;
        int tok = ok ? g_rowtok[e * CC + m] : 0;
        aptr[i] = x + (size_t)tok * HH + kq;
        asz[i]  = ok ? 16u : 0u;
        aoff[i] = (unsigned)(r * AS + kq) * 4u;
    }
    int bn = tid >> 2, bkq = (tid & 3) * 4;
    const float* bgp = wg + ((size_t)e * II + n0 + bn) * HH + bkq;
    const float* bup = wu + ((size_t)e * II + n0 + bn) * HH + bkq;
    unsigned boff = (unsigned)(bn * AS + bkq) * 4u;

    unsigned sA  = (unsigned)__cvta_generic_to_shared(&As_[0][0]);
    unsigned sBg = (unsigned)__cvta_generic_to_shared(&Bg_[0][0]);
    unsigned sBu = (unsigned)__cvta_generic_to_shared(&Bu_[0][0]);
    const unsigned strA = 128 * AS * 4, strB = 64 * AS * 4;

    int warp = tid >> 5, lane = tid & 31;
    int wm = (warp & 3) * 32, wn = (warp >> 2) * 32;
    int gq = lane >> 2, t = lane & 3;

    float cg[2][4][4] = {}, cu[2][4][4] = {};

    // prologue
    cpa(sA + aoff[0], aptr[0], asz[0]);
    cpa(sA + aoff[1], aptr[1], asz[1]);
    cpa(sBg + boff, bgp, 16);
    cpa(sBu + boff, bup, 16);
    CP_COMMIT;

    const int NK = HH / 16;
    for (int kt = 0; kt < NK; kt++) {
        if (kt + 1 < NK) {
            int k0 = (kt + 1) * 16;
            unsigned s = (unsigned)((kt + 1) & 1);
            cpa(sA + s * strA + aoff[0], aptr[0] + k0, asz[0]);
            cpa(sA + s * strA + aoff[1], aptr[1] + k0, asz[1]);
            cpa(sBg + s * strB + boff, bgp + k0, 16);
            cpa(sBu + s * strB + boff, bup + k0, 16);
            CP_COMMIT;
            CP_WAIT1;
        } else {
            CP_WAIT0;
        }
        __syncthreads();

        const float* A  = As_[kt & 1];
        const float* Bg = Bg_[kt & 1];
        const float* Bu = Bu_[kt & 1];
        #pragma unroll
        for (int ks = 0; ks < 2; ks++) {
            unsigned a[2][4];
            #pragma unroll
            for (int im = 0; im < 2; im++) {
                int r = wm + im * 16 + gq;
                a[im][0] = f2tf(A[r * AS + ks * 8 + t]);
                a[im][1] = f2tf(A[(r + 8) * AS + ks * 8 + t]);
                a[im][2] = f2tf(A[r * AS + ks * 8 + t + 4]);
                a[im][3] = f2tf(A[(r + 8) * AS + ks * 8 + t + 4]);
            }
            #pragma unroll
            for (int nt = 0; nt < 4; nt++) {
                int n = wn + nt * 8 + gq;
                unsigned bg0 = f2tf(Bg[n * AS + ks * 8 + t]);
                unsigned bg1 = f2tf(Bg[n * AS + ks * 8 + t + 4]);
                unsigned bu0 = f2tf(Bu[n * AS + ks * 8 + t]);
                unsigned bu1 = f2tf(Bu[n * AS + ks * 8 + t + 4]);
                #pragma unroll
                for (int im = 0; im < 2; im++) {
                    mma8(cg[im][nt], a[im], bg0, bg1);
                    mma8(cu[im][nt], a[im], bu0, bu1);
                }
            }
        }
        __syncthreads();
    }

    // epilogue: SiLU(g)*u -> g_h
    #pragma unroll
    for (int im = 0; im < 2; im++) {
        #pragma unroll
        for (int half = 0; half < 2; half++) {
            int m = m0 + wm + im * 16 + gq + half * 8;
            if (m < cnt) {
                float* dst = &g_h[((size_t)e * CC + m) * II + n0 + wn];
                #pragma unroll
                for (int nt = 0; nt < 4; nt++) {
                    float g0 = cg[im][nt][half * 2],     g1 = cg[im][nt][half * 2 + 1];
                    float u0 = cu[im][nt][half * 2],     u1 = cu[im][nt][half * 2 + 1];
                    float r0 = g0 * (1.f / (1.f + expf(-g0))) * u0;
                    float r1 = g1 * (1.f / (1.f + expf(-g1))) * u1;
                    *(float2*)(dst + nt * 8 + t * 2) = make_float2(r0, r1);
                }
            }
        }
    }
}

// ---------------------------------------------------------------------------
// GEMM2 (tf32 tensor core): g_h[128 x I] x w_down[128 x I]^T, weighted
// atomic scatter-add into out. BM=128, BN=128, warp tile 32 x 64.
// ---------------------------------------------------------------------------
__global__ __launch_bounds__(256) void gemm2_kernel(
    const float* __restrict__ wd,
    float* __restrict__ out)
{
    int e   = blockIdx.z;
    int cnt = min(g_cnt[e], CC);
    int m0  = blockIdx.y * 128;
    if (m0 >= cnt) return;
    int n0  = blockIdx.x * 128;

    __shared__ float As_[2][128 * AS];
    __shared__ float Bs_[2][128 * AS];

    int tid = threadIdx.x;

    const float* aptr[2]; const float* bptr[2]; unsigned off[2];
    #pragma unroll
    for (int i = 0; i < 2; i++) {
        int chunk = tid + i * 256;
        int r = chunk >> 2, kq = (chunk & 3) * 4;
        aptr[i] = &g_h[((size_t)e * CC + m0 + r) * II + kq];  // stale rows >= cnt are discarded
        bptr[i] = wd + ((size_t)e * HH + n0 + r) * II + kq;
        off[i]  = (unsigned)(r * AS + kq) * 4u;
    }
    unsigned sA = (unsigned)__cvta_generic_to_shared(&As_[0][0]);
    unsigned sB = (unsigned)__cvta_generic_to_shared(&Bs_[0][0]);
    const unsigned str = 128 * AS * 4;

    int warp = tid >> 5, lane = tid & 31;
    int wm = (warp & 3) * 32, wn = (warp >> 2) * 64;
    int gq = lane >> 2, t = lane & 3;

    float acc[2][8][4] = {};

    cpa(sA + off[0], aptr[0], 16);
    cpa(sA + off[1], aptr[1], 16);
    cpa(sB + off[0], bptr[0], 16);
    cpa(sB + off[1], bptr[1], 16);
    CP_COMMIT;

    const int NK = II / 16;
    for (int kt = 0; kt < NK; kt++) {
        if (kt + 1 < NK) {
            int k0 = (kt + 1) * 16;
            unsigned s = (unsigned)((kt + 1) & 1);
            cpa(sA + s * str + off[0], aptr[0] + k0, 16);
            cpa(sA + s * str + off[1], aptr[1] + k0, 16);
            cpa(sB + s * str + off[0], bptr[0] + k0, 16);
            cpa(sB + s * str + off[1], bptr[1] + k0, 16);
            CP_COMMIT;
            CP_WAIT1;
        } else {
            CP_WAIT0;
        }
        __syncthreads();

        const float* A = As_[kt & 1];
        const float* B = Bs_[kt & 1];
        #pragma unroll
        for (int ks = 0; ks < 2; ks++) {
            unsigned a[2][4];
            #pragma unroll
            for (int im = 0; im < 2; im++) {
                int r = wm + im * 16 + gq;
                a[im][0] = f2tf(A[r * AS + ks * 8 + t]);
                a[im][1] = f2tf(A[(r + 8) * AS + ks * 8 + t]);
                a[im][2] = f2tf(A[r * AS + ks * 8 + t + 4]);
                a[im][3] = f2tf(A[(r + 8) * AS + ks * 8 + t + 4]);
            }
            #pragma unroll
            for (int nt = 0; nt < 8; nt++) {
                int n = wn + nt * 8 + gq;
                unsigned b0 = f2tf(B[n * AS + ks * 8 + t]);
                unsigned b1 = f2tf(B[n * AS + ks * 8 + t + 4]);
                #pragma unroll
                for (int im = 0; im < 2; im++)
                    mma8(acc[im][nt], a[im], b0, b1);
            }
        }
        __syncthreads();
    }

    // epilogue: weighted atomic scatter-add
    #pragma unroll
    for (int im = 0; im < 2; im++) {
        #pragma unroll
        for (int half = 0; half < 2; half++) {
            int m = m0 + wm + im * 16 + gq + half * 8;
            if (m < cnt) {
                int   tok = g_rowtok[e * CC + m];
                float w   = g_roww[e * CC + m];
                float* op = out + (size_t)tok * HH + n0 + wn;
                #pragma unroll
                for (int nt = 0; nt < 8; nt++) {
                    atomicAdd(op + nt * 8 + t * 2,     w * acc[im][nt][half * 2]);
                    atomicAdd(op + nt * 8 + t * 2 + 1, w * acc[im][nt][half * 2 + 1]);
                }
            }
        }
    }
}

// ---------------------------------------------------------------------------
extern "C" void kernel_launch(void* const* d_in, const int* in_sizes, int n_in,
                              void* d_out, int out_size)
{
    const float* x      = (const float*)d_in[0];
    const float* gw     = (const float*)d_in[1];
    const float* bias   = (const float*)d_in[2];
    const float* w_gate = (const float*)d_in[3];
    const float* w_up   = (const float*)d_in[4];
    const float* w_down = (const float*)d_in[5];
    float* out = (float*)d_out;

    zero_cnt_kernel<<<1, 64>>>();
    zero_out_kernel<<<(TT * HH / 4) / 256, 256>>>((float4*)out);
    router_kernel<<<TT / 16, 256>>>(x, gw, bias);
    gemm1_kernel<<<dim3(II / 64, CC / 128, EE), 256>>>(x, w_gate, w_up);
    gemm2_kernel<<<dim3(HH / 128, CC / 128, EE), 256>>>(w_down, out);
}

// round 3
// speedup vs baseline: 4.6050x; 1.2965x over previous
#include <cuda_runtime.h>
#include <cuda_fp16.h>
#include <math.h>

#define TT 4096
#define HH 1536
#define II 768
#define EE 64
#define KK 8
#define CC 1024

// Scratch (no allocation allowed).
__device__ int    g_cnt[EE];
__device__ int    g_rowtok[EE * CC];
__device__ float  g_roww[EE * CC];
__device__ __half g_xh[(size_t)TT * HH];          // fp16 copy of hidden_states
__device__ __half g_h[(size_t)EE * CC * II];      // SwiGLU activations, fp16

// ---------------------------------------------------------------------------
// helpers
// ---------------------------------------------------------------------------
__device__ __forceinline__ void mma16(float* c, const unsigned* a, unsigned b0, unsigned b1) {
    asm volatile(
        "mma.sync.aligned.m16n8k16.row.col.f32.f16.f16.f32 "
        "{%0,%1,%2,%3}, {%4,%5,%6,%7}, {%8,%9}, {%0,%1,%2,%3};\n"
        : "+f"(c[0]), "+f"(c[1]), "+f"(c[2]), "+f"(c[3])
        : "r"(a[0]), "r"(a[1]), "r"(a[2]), "r"(a[3]), "r"(b0), "r"(b1));
}
__device__ __forceinline__ void cpa(unsigned dst, const void* src, unsigned sz) {
    asm volatile("cp.async.cg.shared.global [%0], [%1], 16, %2;\n"
                 :: "r"(dst), "l"(src), "r"(sz));
}
#define CP_COMMIT asm volatile("cp.async.commit_group;\n")
#define CP_WAIT1  asm volatile("cp.async.wait_group 1;\n")

__global__ void zero_cnt_kernel() {
    if (threadIdx.x < EE) g_cnt[threadIdx.x] = 0;
}
__global__ void zero_out_kernel(float4* out) {
    int i = blockIdx.x * blockDim.x + threadIdx.x;
    out[i] = make_float4(0.f, 0.f, 0.f, 0.f);
}
__global__ void f2h_x_kernel(const float4* __restrict__ src) {
    int i = blockIdx.x * blockDim.x + threadIdx.x;   // i < TT*HH/8
    float4 v0 = src[2 * i], v1 = src[2 * i + 1];
    __half2 h0 = __floats2half2_rn(v0.x, v0.y);
    __half2 h1 = __floats2half2_rn(v0.z, v0.w);
    __half2 h2 = __floats2half2_rn(v1.x, v1.y);
    __half2 h3 = __floats2half2_rn(v1.z, v1.w);
    uint4 o;
    o.x = *(unsigned*)&h0; o.y = *(unsigned*)&h1;
    o.z = *(unsigned*)&h2; o.w = *(unsigned*)&h3;
    ((uint4*)g_xh)[i] = o;
}

// ---------------------------------------------------------------------------
// Router: exact fp32 (top-k selection is tie-sensitive; keep full precision).
// ---------------------------------------------------------------------------
__global__ __launch_bounds__(256) void router_kernel(
    const float* __restrict__ x,
    const float* __restrict__ gw,
    const float* __restrict__ bias)
{
    __shared__ float xs[16][65];
    __shared__ float gs[64][65];
    __shared__ float s_sel[16][64];
    __shared__ float s_sc[16][64];

    int tid  = threadIdx.x;
    int tok0 = blockIdx.x * 16;
    int t    = tid >> 4;
    int eg   = tid & 15;

    float acc[4] = {0.f, 0.f, 0.f, 0.f};

    for (int c = 0; c < HH / 64; c++) {
        int h0 = c * 64;
        __syncthreads();
        {
            int r = tid >> 4, hq = (tid & 15) << 2;
            float4 v = *(const float4*)(x + (size_t)(tok0 + r) * HH + h0 + hq);
            xs[r][hq] = v.x; xs[r][hq + 1] = v.y; xs[r][hq + 2] = v.z; xs[r][hq + 3] = v.w;
        }
        #pragma unroll
        for (int r4 = 0; r4 < 4; r4++) {
            int idx = tid + r4 * 256;
            int e2 = idx >> 4, hq = (idx & 15) << 2;
            float4 v = *(const float4*)(gw + (size_t)e2 * HH + h0 + hq);
            gs[e2][hq] = v.x; gs[e2][hq + 1] = v.y; gs[e2][hq + 2] = v.z; gs[e2][hq + 3] = v.w;
        }
        __syncthreads();
        #pragma unroll 8
        for (int h = 0; h < 64; h++) {
            float xv = xs[t][h];
            #pragma unroll
            for (int j = 0; j < 4; j++)
                acc[j] = fmaf(xv, gs[eg + 16 * j][h], acc[j]);
        }
    }

    #pragma unroll
    for (int j = 0; j < 4; j++) {
        int e = eg + 16 * j;
        float sc = 1.f / (1.f + expf(-acc[j]));
        s_sc[t][e]  = sc;
        s_sel[t][e] = sc + bias[e];
    }
    __syncthreads();

    int warp = tid >> 5, lane = tid & 31;
    for (int tt = warp; tt < 16; tt += 8) {
        float v0 = s_sel[tt][lane];
        float v1 = s_sel[tt][lane + 32];
        int bid[KK];
        float wsum = 0.f;
        #pragma unroll
        for (int k = 0; k < KK; k++) {
            float v; int id;
            if (v0 >= v1) { v = v0; id = lane; } else { v = v1; id = lane + 32; }
            #pragma unroll
            for (int off = 16; off; off >>= 1) {
                float ov = __shfl_xor_sync(0xffffffffu, v, off);
                int   oi = __shfl_xor_sync(0xffffffffu, id, off);
                if (ov > v || (ov == v && oi < id)) { v = ov; id = oi; }
            }
            bid[k] = id;
            wsum += s_sc[tt][id];
            if (id == lane)      v0 = -1e30f;
            if (id == lane + 32) v1 = -1e30f;
        }
        if (lane < KK) {
            int e = bid[lane];
            float wgt = s_sc[tt][e] / wsum;
            int pos = atomicAdd(&g_cnt[e], 1);
            if (pos < CC) {
                g_rowtok[e * CC + pos] = tok0 + tt;
                g_roww[e * CC + pos]   = wgt;
            }
        }
    }
}

// ---------------------------------------------------------------------------
// GEMM1 (fp16 mma m16n8k16): gathered A[128 x K] (fp16) x {w_gate,w_up}
// [128 x K]^T (fp32 in smem, cvt in-register), SiLU(g)*u -> g_h (fp16).
// BM=128, BN=128 (g and u), BK=32, 8 warps (2m x 4n), warp tile 64x32,
// 3-stage cp.async pipeline, one __syncthreads per K-step.
// ---------------------------------------------------------------------------
#define G1_AB   (128 * 40 * 2)          // A stage bytes (128 rows x 40 halves)
#define G1_BB   (256 * 36 * 4)          // B stage bytes (256 rows x 36 floats)
#define G1_STG  (G1_AB + G1_BB)

__global__ __launch_bounds__(256, 1) void gemm1_kernel(
    const float* __restrict__ wg,
    const float* __restrict__ wu)
{
    extern __shared__ char smem[];
    int e   = blockIdx.z;
    int cnt = min(g_cnt[e], CC);
    int m0  = blockIdx.y * 128;
    if (m0 >= cnt) return;
    int n0  = blockIdx.x * 128;

    int tid = threadIdx.x;
    unsigned sbase = (unsigned)__cvta_generic_to_shared(smem);

    // A fill setup: 512 x 16B chunks (rows of 64B), 2 per thread; gathered tokens.
    const __half* aptr[2]; unsigned asz[2]; unsigned aoff[2];
    #pragma unroll
    for (int i = 0; i < 2; i++) {
        int c = tid + i * 256;
        int r = c >> 2, k8 = (c & 3) * 8;
        int m = m0 + r;
        int ok = m < cnt;
        int tok = ok ? g_rowtok[e * CC + m] : 0;
        aptr[i] = g_xh + (size_t)tok * HH + k8;
        asz[i]  = ok ? 16u : 0u;
        aoff[i] = (unsigned)(r * 40 + k8) * 2u;
    }
    // B fill setup: 2048 x 16B chunks (rows of 128B fp32), 8 per thread.
    const float* bptr[8]; unsigned boff[8];
    #pragma unroll
    for (int i = 0; i < 8; i++) {
        int c = tid + i * 256;
        int r = c >> 3, k4 = (c & 7) * 4;
        const float* base = (r < 128)
            ? wg + ((size_t)e * II + n0 + r) * HH
            : wu + ((size_t)e * II + n0 + (r - 128)) * HH;
        bptr[i] = base + k4;
        boff[i] = (unsigned)(G1_AB + (r * 36 + k4) * 4);
    }

    int warp = tid >> 5, lane = tid & 31;
    int wm = (warp & 1) * 64, wn = (warp >> 1) * 32;
    int gq = lane >> 2, t = lane & 3;

    float acc[2][4][4][4] = {};   // [kind][im][nt][c]

    // prologue: stages 0,1
    #pragma unroll
    for (int s = 0; s < 2; s++) {
        int k0 = s * 32;
        unsigned so = sbase + s * G1_STG;
        #pragma unroll
        for (int i = 0; i < 2; i++) cpa(so + aoff[i], aptr[i] + k0, asz[i]);
        #pragma unroll
        for (int i = 0; i < 8; i++) cpa(so + boff[i], bptr[i] + k0, 16);
        CP_COMMIT;
    }

    const int NK = HH / 32;
    int s = 0;
    for (int kt = 0; kt < NK; kt++) {
        CP_WAIT1;
        __syncthreads();
        if (kt + 2 < NK) {
            int k0 = (kt + 2) * 32;
            int s2 = s + 2; if (s2 >= 3) s2 -= 3;
            unsigned so = sbase + s2 * G1_STG;
            #pragma unroll
            for (int i = 0; i < 2; i++) cpa(so + aoff[i], aptr[i] + k0, asz[i]);
            #pragma unroll
            for (int i = 0; i < 8; i++) cpa(so + boff[i], bptr[i] + k0, 16);
        }
        CP_COMMIT;

        const __half* Ah = (const __half*)(smem + s * G1_STG);
        const float*  Bf = (const float*)(smem + s * G1_STG + G1_AB);
        #pragma unroll
        for (int ks = 0; ks < 2; ks++) {
            unsigned a[4][4];
            #pragma unroll
            for (int im = 0; im < 4; im++) {
                const __half* ap = Ah + (wm + im * 16 + gq) * 40 + ks * 16 + 2 * t;
                a[im][0] = *(const unsigned*)ap;
                a[im][1] = *(const unsigned*)(ap + 8 * 40);
                a[im][2] = *(const unsigned*)(ap + 8);
                a[im][3] = *(const unsigned*)(ap + 8 * 40 + 8);
            }
            #pragma unroll
            for (int nt = 0; nt < 4; nt++) {
                int nrow = wn + nt * 8 + gq;
                #pragma unroll
                for (int kind = 0; kind < 2; kind++) {
                    const float* bp = Bf + (nrow + kind * 128) * 36 + ks * 16 + 2 * t;
                    float2 f0 = *(const float2*)bp;
                    float2 f1 = *(const float2*)(bp + 8);
                    __half2 h0 = __floats2half2_rn(f0.x, f0.y);
                    __half2 h1 = __floats2half2_rn(f1.x, f1.y);
                    unsigned b0 = *(unsigned*)&h0, b1 = *(unsigned*)&h1;
                    #pragma unroll
                    for (int im = 0; im < 4; im++)
                        mma16(acc[kind][im][nt], a[im], b0, b1);
                }
            }
        }
        if (++s >= 3) s -= 3;
    }

    // epilogue: SiLU(g)*u -> g_h (fp16)
    #pragma unroll
    for (int im = 0; im < 4; im++) {
        #pragma unroll
        for (int h2 = 0; h2 < 2; h2++) {
            int m = m0 + wm + im * 16 + gq + h2 * 8;
            if (m < cnt) {
                __half* dst = g_h + ((size_t)e * CC + m) * II + n0 + wn + 2 * t;
                #pragma unroll
                for (int nt = 0; nt < 4; nt++) {
                    float g0 = acc[0][im][nt][h2 * 2],     g1 = acc[0][im][nt][h2 * 2 + 1];
                    float u0 = acc[1][im][nt][h2 * 2],     u1 = acc[1][im][nt][h2 * 2 + 1];
                    float r0 = g0 * (1.f / (1.f + expf(-g0))) * u0;
                    float r1 = g1 * (1.f / (1.f + expf(-g1))) * u1;
                    *(__half2*)(dst + nt * 8) = __floats2half2_rn(r0, r1);
                }
            }
        }
    }
}

// ---------------------------------------------------------------------------
// GEMM2 (fp16 mma): g_h[128 x I] (fp16) x w_down[128 x I]^T (fp32 smem),
// weighted atomic scatter-add into out. BM=128, BN=128, BK=32, warp 64x32.
// ---------------------------------------------------------------------------
#define G2_AB   (128 * 40 * 2)
#define G2_BB   (128 * 36 * 4)
#define G2_STG  (G2_AB + G2_BB)

__global__ __launch_bounds__(256, 1) void gemm2_kernel(
    const float* __restrict__ wd,
    float* __restrict__ out)
{
    extern __shared__ char smem[];
    int e   = blockIdx.z;
    int cnt = min(g_cnt[e], CC);
    int m0  = blockIdx.y * 128;
    if (m0 >= cnt) return;
    int n0  = blockIdx.x * 128;

    int tid = threadIdx.x;
    unsigned sbase = (unsigned)__cvta_generic_to_shared(smem);

    const __half* aptr[2]; unsigned aoff[2];
    #pragma unroll
    for (int i = 0; i < 2; i++) {
        int c = tid + i * 256;
        int r = c >> 2, k8 = (c & 3) * 8;
        aptr[i] = g_h + ((size_t)e * CC + m0 + r) * II + k8;  // stale rows >= cnt masked later
        aoff[i] = (unsigned)(r * 40 + k8) * 2u;
    }
    const float* bptr[4]; unsigned boff[4];
    #pragma unroll
    for (int i = 0; i < 4; i++) {
        int c = tid + i * 256;
        int r = c >> 3, k4 = (c & 7) * 4;
        bptr[i] = wd + ((size_t)e * HH + n0 + r) * II + k4;
        boff[i] = (unsigned)(G2_AB + (r * 36 + k4) * 4);
    }

    int warp = tid >> 5, lane = tid & 31;
    int wm = (warp & 1) * 64, wn = (warp >> 1) * 32;
    int gq = lane >> 2, t = lane & 3;

    float acc[4][4][4] = {};   // [im][nt][c]

    #pragma unroll
    for (int s = 0; s < 2; s++) {
        int k0 = s * 32;
        unsigned so = sbase + s * G2_STG;
        #pragma unroll
        for (int i = 0; i < 2; i++) cpa(so + aoff[i], aptr[i] + k0, 16);
        #pragma unroll
        for (int i = 0; i < 4; i++) cpa(so + boff[i], bptr[i] + k0, 16);
        CP_COMMIT;
    }

    const int NK = II / 32;
    int s = 0;
    for (int kt = 0; kt < NK; kt++) {
        CP_WAIT1;
        __syncthreads();
        if (kt + 2 < NK) {
            int k0 = (kt + 2) * 32;
            int s2 = s + 2; if (s2 >= 3) s2 -= 3;
            unsigned so = sbase + s2 * G2_STG;
            #pragma unroll
            for (int i = 0; i < 2; i++) cpa(so + aoff[i], aptr[i] + k0, 16);
            #pragma unroll
            for (int i = 0; i < 4; i++) cpa(so + boff[i], bptr[i] + k0, 16);
        }
        CP_COMMIT;

        const __half* Ah = (const __half*)(smem + s * G2_STG);
        const float*  Bf = (const float*)(smem + s * G2_STG + G2_AB);
        #pragma unroll
        for (int ks = 0; ks < 2; ks++) {
            unsigned a[4][4];
            #pragma unroll
            for (int im = 0; im < 4; im++) {
                const __half* ap = Ah + (wm + im * 16 + gq) * 40 + ks * 16 + 2 * t;
                a[im][0] = *(const unsigned*)ap;
                a[im][1] = *(const unsigned*)(ap + 8 * 40);
                a[im][2] = *(const unsigned*)(ap + 8);
                a[im][3] = *(const unsigned*)(ap + 8 * 40 + 8);
            }
            #pragma unroll
            for (int nt = 0; nt < 4; nt++) {
                const float* bp = Bf + (wn + nt * 8 + gq) * 36 + ks * 16 + 2 * t;
                float2 f0 = *(const float2*)bp;
                float2 f1 = *(const float2*)(bp + 8);
                __half2 h0 = __floats2half2_rn(f0.x, f0.y);
                __half2 h1 = __floats2half2_rn(f1.x, f1.y);
                unsigned b0 = *(unsigned*)&h0, b1 = *(unsigned*)&h1;
                #pragma unroll
                for (int im = 0; im < 4; im++)
                    mma16(acc[im][nt], a[im], b0, b1);
            }
        }
        if (++s >= 3) s -= 3;
    }

    // epilogue: weighted atomic scatter-add
    #pragma unroll
    for (int im = 0; im < 4; im++) {
        #pragma unroll
        for (int h2 = 0; h2 < 2; h2++) {
            int m = m0 + wm + im * 16 + gq + h2 * 8;
            if (m < cnt) {
                int   tok = g_rowtok[e * CC + m];
                float w   = g_roww[e * CC + m];
                float* op = out + (size_t)tok * HH + n0 + wn + 2 * t;
                #pragma unroll
                for (int nt = 0; nt < 4; nt++) {
                    atomicAdd(op + nt * 8,     w * acc[im][nt][h2 * 2]);
                    atomicAdd(op + nt * 8 + 1, w * acc[im][nt][h2 * 2 + 1]);
                }
            }
        }
    }
}

// ---------------------------------------------------------------------------
extern "C" void kernel_launch(void* const* d_in, const int* in_sizes, int n_in,
                              void* d_out, int out_size)
{
    const float* x      = (const float*)d_in[0];
    const float* gw     = (const float*)d_in[1];
    const float* bias   = (const float*)d_in[2];
    const float* w_gate = (const float*)d_in[3];
    const float* w_up   = (const float*)d_in[4];
    const float* w_down = (const float*)d_in[5];
    float* out = (float*)d_out;

    cudaFuncSetAttribute(gemm1_kernel, cudaFuncAttributeMaxDynamicSharedMemorySize, 3 * G1_STG);
    cudaFuncSetAttribute(gemm2_kernel, cudaFuncAttributeMaxDynamicSharedMemorySize, 3 * G2_STG);

    zero_cnt_kernel<<<1, 64>>>();
    zero_out_kernel<<<(TT * HH / 4) / 256, 256>>>((float4*)out);
    f2h_x_kernel<<<(TT * HH / 8) / 256, 256>>>((const float4*)x);
    router_kernel<<<TT / 16, 256>>>(x, gw, bias);
    gemm1_kernel<<<dim3(II / 128, CC / 128, EE), 256, 3 * G1_STG>>>(w_gate, w_up);
    gemm2_kernel<<<dim3(HH / 128, CC / 128, EE), 256, 3 * G2_STG>>>(w_down, out);
}

// round 4
// speedup vs baseline: 5.1386x; 1.1159x over previous
#include <cuda_runtime.h>
#include <cuda_fp16.h>
#include <math.h>

#define TT 4096
#define HH 1536
#define II 768
#define EE 64
#define KK 8
#define CC 1024

// Scratch (no allocation allowed).
__device__ int    g_cnt[EE];
__device__ int    g_rowtok[EE * CC];
__device__ float  g_roww[EE * CC];
__device__ float  g_logits[(size_t)TT * EE];
__device__ __half g_xh[(size_t)TT * HH];            // fp16 hidden_states
__device__ __half g_h[(size_t)EE * CC * II];        // SwiGLU activations fp16
__device__ __half g_wgh[(size_t)EE * II * HH];      // fp16 w_gate
__device__ __half g_wuh[(size_t)EE * II * HH];      // fp16 w_up
__device__ __half g_wdh[(size_t)EE * HH * II];      // fp16 w_down

// ---------------------------------------------------------------------------
// helpers
// ---------------------------------------------------------------------------
__device__ __forceinline__ void mma16(float* c, const unsigned* a, unsigned b0, unsigned b1) {
    asm volatile(
        "mma.sync.aligned.m16n8k16.row.col.f32.f16.f16.f32 "
        "{%0,%1,%2,%3}, {%4,%5,%6,%7}, {%8,%9}, {%0,%1,%2,%3};\n"
        : "+f"(c[0]), "+f"(c[1]), "+f"(c[2]), "+f"(c[3])
        : "r"(a[0]), "r"(a[1]), "r"(a[2]), "r"(a[3]), "r"(b0), "r"(b1));
}
__device__ __forceinline__ void ldsm4(unsigned& r0, unsigned& r1, unsigned& r2, unsigned& r3,
                                      unsigned addr) {
    asm volatile("ldmatrix.sync.aligned.m8n8.x4.shared.b16 {%0,%1,%2,%3}, [%4];"
                 : "=r"(r0), "=r"(r1), "=r"(r2), "=r"(r3) : "r"(addr));
}
__device__ __forceinline__ void cpa(unsigned dst, const void* src, unsigned sz) {
    asm volatile("cp.async.cg.shared.global [%0], [%1], 16, %2;\n"
                 :: "r"(dst), "l"(src), "r"(sz));
}
#define CP_COMMIT asm volatile("cp.async.commit_group;\n")
#define CP_WAIT1  asm volatile("cp.async.wait_group 1;\n")

__global__ void zero_cnt_kernel() {
    if (threadIdx.x < EE) g_cnt[threadIdx.x] = 0;
}
__global__ void zero_out_kernel(float4* out) {
    int i = blockIdx.x * blockDim.x + threadIdx.x;
    out[i] = make_float4(0.f, 0.f, 0.f, 0.f);
}
// generic fp32 -> fp16 (8 elements / thread)
__global__ void f2h_kernel(const float4* __restrict__ src, uint4* __restrict__ dst) {
    size_t i = (size_t)blockIdx.x * blockDim.x + threadIdx.x;
    float4 v0 = src[2 * i], v1 = src[2 * i + 1];
    __half2 h0 = __floats2half2_rn(v0.x, v0.y);
    __half2 h1 = __floats2half2_rn(v0.z, v0.w);
    __half2 h2 = __floats2half2_rn(v1.x, v1.y);
    __half2 h3 = __floats2half2_rn(v1.z, v1.w);
    uint4 o;
    o.x = *(unsigned*)&h0; o.y = *(unsigned*)&h1;
    o.z = *(unsigned*)&h2; o.w = *(unsigned*)&h3;
    dst[i] = o;
}

// ---------------------------------------------------------------------------
// Router part 1: logits = x @ gate_w^T in exact fp32. BM=64 tok, BN=64 exp,
// BK=16, 256 threads, 4x4 per thread.
// ---------------------------------------------------------------------------
__global__ __launch_bounds__(256) void logits_kernel(
    const float* __restrict__ x,
    const float* __restrict__ gw)
{
    __shared__ float As[16][64];
    __shared__ float Bs[16][64];

    int tid  = threadIdx.x;
    int tok0 = blockIdx.x * 64;

    int lrow = tid >> 2;
    int lkq  = (tid & 3) << 2;
    const float* ap = x  + (size_t)(tok0 + lrow) * HH + lkq;
    const float* bp = gw + (size_t)lrow * HH + lkq;

    int tx = (tid & 15) << 2;
    int ty = (tid >> 4) << 2;

    float acc[4][4] = {};

    for (int k0 = 0; k0 < HH; k0 += 16) {
        float4 av = *(const float4*)(ap + k0);
        float4 bv = *(const float4*)(bp + k0);
        __syncthreads();
        As[lkq][lrow] = av.x; As[lkq + 1][lrow] = av.y; As[lkq + 2][lrow] = av.z; As[lkq + 3][lrow] = av.w;
        Bs[lkq][lrow] = bv.x; Bs[lkq + 1][lrow] = bv.y; Bs[lkq + 2][lrow] = bv.z; Bs[lkq + 3][lrow] = bv.w;
        __syncthreads();
        #pragma unroll
        for (int k = 0; k < 16; k++) {
            float4 a = *(const float4*)&As[k][ty];
            float4 b = *(const float4*)&Bs[k][tx];
            float aa[4] = {a.x, a.y, a.z, a.w};
            float bb[4] = {b.x, b.y, b.z, b.w};
            #pragma unroll
            for (int i = 0; i < 4; i++)
                #pragma unroll
                for (int j = 0; j < 4; j++)
                    acc[i][j] = fmaf(aa[i], bb[j], acc[i][j]);
        }
    }
    #pragma unroll
    for (int i = 0; i < 4; i++)
        #pragma unroll
        for (int j = 0; j < 4; j++)
            g_logits[(size_t)(tok0 + ty + i) * EE + tx + j] = acc[i][j];
}

// ---------------------------------------------------------------------------
// Router part 2: sigmoid + bias + top-8 + atomic dispatch. Warp per token.
// ---------------------------------------------------------------------------
__global__ __launch_bounds__(512) void topk_kernel(const float* __restrict__ bias)
{
    int warp = threadIdx.x >> 5, lane = threadIdx.x & 31;
    int tok  = blockIdx.x * 16 + warp;

    float l0 = g_logits[(size_t)tok * EE + lane];
    float l1 = g_logits[(size_t)tok * EE + lane + 32];
    float sc0 = 1.f / (1.f + expf(-l0));
    float sc1 = 1.f / (1.f + expf(-l1));
    float v0 = sc0 + bias[lane];
    float v1 = sc1 + bias[lane + 32];

    int   my_e = -1;
    float wsum = 0.f;
    #pragma unroll
    for (int k = 0; k < KK; k++) {
        float v; int id;
        if (v0 >= v1) { v = v0; id = lane; } else { v = v1; id = lane + 32; }
        #pragma unroll
        for (int off = 16; off; off >>= 1) {
            float ov = __shfl_xor_sync(0xffffffffu, v, off);
            int   oi = __shfl_xor_sync(0xffffffffu, id, off);
            if (ov > v || (ov == v && oi < id)) { v = ov; id = oi; }
        }
        float s0 = __shfl_sync(0xffffffffu, sc0, id & 31);
        float s1 = __shfl_sync(0xffffffffu, sc1, id & 31);
        wsum += (id < 32) ? s0 : s1;
        if (k == lane) my_e = id;
        if (id == lane)      v0 = -1e30f;
        if (id == lane + 32) v1 = -1e30f;
    }
    if (lane < KK) {
        int e = my_e;
        float s0 = __shfl_sync(0x000000ffu, sc0, e & 31, 8);
        // can't subgroup-shuffle across full warp reliably here; recompute via full warp below
        (void)s0;
    }
    // fetch score of my_e with full-warp shuffles (uniform participation)
    {
        int src = (my_e >= 0) ? (my_e & 31) : 0;
        float s0 = __shfl_sync(0xffffffffu, sc0, src);
        float s1 = __shfl_sync(0xffffffffu, sc1, src);
        if (lane < KK) {
            float wgt = ((my_e < 32) ? s0 : s1) / wsum;
            int pos = atomicAdd(&g_cnt[my_e], 1);
            if (pos < CC) {
                g_rowtok[my_e * CC + pos] = tok;
                g_roww[my_e * CC + pos]   = wgt;
            }
        }
    }
}

// ---------------------------------------------------------------------------
// GEMM1 (fp16 mma + ldmatrix): A = gathered tokens [128 x K], B = fp16
// {w_gate,w_up} [256 x K], SiLU(g)*u -> g_h. BM=128, BN=128, BK=32,
// 8 warps (2m x 4n), warp tile 64 x (32g+32u), 3-stage cp.async.
// ---------------------------------------------------------------------------
#define G1_AB   (128 * 40 * 2)
#define G1_BB   (256 * 40 * 2)
#define G1_STG  (G1_AB + G1_BB)

__global__ __launch_bounds__(256, 1) void gemm1_kernel()
{
    extern __shared__ char smem[];
    int e   = blockIdx.z;
    int cnt = min(g_cnt[e], CC);
    int m0  = blockIdx.y * 128;
    if (m0 >= cnt) return;
    int n0  = blockIdx.x * 128;

    int tid = threadIdx.x;
    unsigned sbase = (unsigned)__cvta_generic_to_shared(smem);

    // A fill: 512 chunks of 16B (rows of 64B), 2 per thread; gathered tokens.
    const __half* aptr[2]; unsigned asz[2]; unsigned aoff[2];
    #pragma unroll
    for (int i = 0; i < 2; i++) {
        int c = tid + i * 256;
        int r = c >> 2, k8 = (c & 3) * 8;
        int m = m0 + r;
        int ok = m < cnt;
        int tok = ok ? g_rowtok[e * CC + m] : 0;
        aptr[i] = g_xh + (size_t)tok * HH + k8;
        asz[i]  = ok ? 16u : 0u;
        aoff[i] = (unsigned)(r * 40 + k8) * 2u;
    }
    // B fill: 1024 chunks, 4 per thread (rows: 0-127 gate, 128-255 up).
    const __half* bptr[4]; unsigned boff[4];
    #pragma unroll
    for (int i = 0; i < 4; i++) {
        int c = tid + i * 256;
        int r = c >> 2, k8 = (c & 3) * 8;
        const __half* base = (r < 128)
            ? g_wgh + ((size_t)e * II + n0 + r) * HH
            : g_wuh + ((size_t)e * II + n0 + (r - 128)) * HH;
        bptr[i] = base + k8;
        boff[i] = (unsigned)(G1_AB + (r * 40 + k8) * 2);
    }

    int warp = tid >> 5, lane = tid & 31;
    int wm = (warp & 1) * 64, wn = (warp >> 1) * 32;
    int gq = lane >> 2, t = lane & 3;

    // ldmatrix lane offsets (bytes)
    unsigned a_lane = (unsigned)(((lane & 15) * 40 + (lane >> 4) * 8) * 2);
    unsigned b_lane = (unsigned)(((((lane & 7) + ((lane >> 4) & 1) * 8)) * 40
                                  + ((lane >> 3) & 1) * 8) * 2);

    float acc[2][4][4][4] = {};   // [kind][im][nt][c]

    #pragma unroll
    for (int s = 0; s < 2; s++) {
        int k0 = s * 32;
        unsigned so = sbase + s * G1_STG;
        #pragma unroll
        for (int i = 0; i < 2; i++) cpa(so + aoff[i], aptr[i] + k0, asz[i]);
        #pragma unroll
        for (int i = 0; i < 4; i++) cpa(so + boff[i], bptr[i] + k0, 16);
        CP_COMMIT;
    }

    const int NK = HH / 32;
    int s = 0;
    for (int kt = 0; kt < NK; kt++) {
        CP_WAIT1;
        __syncthreads();
        if (kt + 2 < NK) {
            int k0 = (kt + 2) * 32;
            int s2 = s + 2; if (s2 >= 3) s2 -= 3;
            unsigned so = sbase + s2 * G1_STG;
            #pragma unroll
            for (int i = 0; i < 2; i++) cpa(so + aoff[i], aptr[i] + k0, asz[i]);
            #pragma unroll
            for (int i = 0; i < 4; i++) cpa(so + boff[i], bptr[i] + k0, 16);
        }
        CP_COMMIT;

        unsigned sA = sbase + s * G1_STG;
        unsigned sB = sA + G1_AB;
        #pragma unroll
        for (int ks = 0; ks < 2; ks++) {
            unsigned a[4][4];
            #pragma unroll
            for (int im = 0; im < 4; im++)
                ldsm4(a[im][0], a[im][1], a[im][2], a[im][3],
                      sA + a_lane + (unsigned)((wm + im * 16) * 80 + ks * 32));
            #pragma unroll
            for (int kind = 0; kind < 2; kind++) {
                #pragma unroll
                for (int ntp = 0; ntp < 2; ntp++) {
                    unsigned b0, b1, b2, b3;
                    ldsm4(b0, b1, b2, b3,
                          sB + b_lane + (unsigned)((kind * 128 + wn + ntp * 16) * 80 + ks * 32));
                    #pragma unroll
                    for (int im = 0; im < 4; im++) {
                        mma16(acc[kind][im][2 * ntp],     a[im], b0, b1);
                        mma16(acc[kind][im][2 * ntp + 1], a[im], b2, b3);
                    }
                }
            }
        }
        if (++s >= 3) s -= 3;
    }

    // epilogue: SiLU(g)*u -> g_h (fp16)
    #pragma unroll
    for (int im = 0; im < 4; im++) {
        #pragma unroll
        for (int h2 = 0; h2 < 2; h2++) {
            int m = m0 + wm + im * 16 + gq + h2 * 8;
            if (m < cnt) {
                __half* dst = g_h + ((size_t)e * CC + m) * II + n0 + wn + 2 * t;
                #pragma unroll
                for (int nt = 0; nt < 4; nt++) {
                    float g0 = acc[0][im][nt][h2 * 2],     g1 = acc[0][im][nt][h2 * 2 + 1];
                    float u0 = acc[1][im][nt][h2 * 2],     u1 = acc[1][im][nt][h2 * 2 + 1];
                    float r0 = g0 * (1.f / (1.f + expf(-g0))) * u0;
                    float r1 = g1 * (1.f / (1.f + expf(-g1))) * u1;
                    *(__half2*)(dst + nt * 8) = __floats2half2_rn(r0, r1);
                }
            }
        }
    }
}

// ---------------------------------------------------------------------------
// GEMM2 (fp16 mma + ldmatrix): g_h[128 x I] x w_down[128 x I]^T fp16,
// weighted atomic scatter-add into out. BM=128, BN=128, BK=32, warp 64x32.
// ---------------------------------------------------------------------------
#define G2_AB   (128 * 40 * 2)
#define G2_BB   (128 * 40 * 2)
#define G2_STG  (G2_AB + G2_BB)

__global__ __launch_bounds__(256, 1) void gemm2_kernel(float* __restrict__ out)
{
    extern __shared__ char smem[];
    int e   = blockIdx.z;
    int cnt = min(g_cnt[e], CC);
    int m0  = blockIdx.y * 128;
    if (m0 >= cnt) return;
    int n0  = blockIdx.x * 128;

    int tid = threadIdx.x;
    unsigned sbase = (unsigned)__cvta_generic_to_shared(smem);

    const __half* aptr[2]; unsigned aoff[2];
    const __half* bptr[2]; unsigned boff[2];
    #pragma unroll
    for (int i = 0; i < 2; i++) {
        int c = tid + i * 256;
        int r = c >> 2, k8 = (c & 3) * 8;
        aptr[i] = g_h + ((size_t)e * CC + m0 + r) * II + k8;   // stale rows >= cnt masked in epilogue
        aoff[i] = (unsigned)(r * 40 + k8) * 2u;
        bptr[i] = g_wdh + ((size_t)e * HH + n0 + r) * II + k8;
        boff[i] = (unsigned)(G2_AB + (r * 40 + k8) * 2);
    }

    int warp = tid >> 5, lane = tid & 31;
    int wm = (warp & 1) * 64, wn = (warp >> 1) * 32;
    int gq = lane >> 2, t = lane & 3;

    unsigned a_lane = (unsigned)(((lane & 15) * 40 + (lane >> 4) * 8) * 2);
    unsigned b_lane = (unsigned)(((((lane & 7) + ((lane >> 4) & 1) * 8)) * 40
                                  + ((lane >> 3) & 1) * 8) * 2);

    float acc[4][4][4] = {};

    #pragma unroll
    for (int s = 0; s < 2; s++) {
        int k0 = s * 32;
        unsigned so = sbase + s * G2_STG;
        #pragma unroll
        for (int i = 0; i < 2; i++) cpa(so + aoff[i], aptr[i] + k0, 16);
        #pragma unroll
        for (int i = 0; i < 2; i++) cpa(so + boff[i], bptr[i] + k0, 16);
        CP_COMMIT;
    }

    const int NK = II / 32;
    int s = 0;
    for (int kt = 0; kt < NK; kt++) {
        CP_WAIT1;
        __syncthreads();
        if (kt + 2 < NK) {
            int k0 = (kt + 2) * 32;
            int s2 = s + 2; if (s2 >= 3) s2 -= 3;
            unsigned so = sbase + s2 * G2_STG;
            #pragma unroll
            for (int i = 0; i < 2; i++) cpa(so + aoff[i], aptr[i] + k0, 16);
            #pragma unroll
            for (int i = 0; i < 2; i++) cpa(so + boff[i], bptr[i] + k0, 16);
        }
        CP_COMMIT;

        unsigned sA = sbase + s * G2_STG;
        unsigned sB = sA + G2_AB;
        #pragma unroll
        for (int ks = 0; ks < 2; ks++) {
            unsigned a[4][4];
            #pragma unroll
            for (int im = 0; im < 4; im++)
                ldsm4(a[im][0], a[im][1], a[im][2], a[im][3],
                      sA + a_lane + (unsigned)((wm + im * 16) * 80 + ks * 32));
            #pragma unroll
            for (int ntp = 0; ntp < 2; ntp++) {
                unsigned b0, b1, b2, b3;
                ldsm4(b0, b1, b2, b3,
                      sB + b_lane + (unsigned)((wn + ntp * 16) * 80 + ks * 32));
                #pragma unroll
                for (int im = 0; im < 4; im++) {
                    mma16(acc[im][2 * ntp],     a[im], b0, b1);
                    mma16(acc[im][2 * ntp + 1], a[im], b2, b3);
                }
            }
        }
        if (++s >= 3) s -= 3;
    }

    #pragma unroll
    for (int im = 0; im < 4; im++) {
        #pragma unroll
        for (int h2 = 0; h2 < 2; h2++) {
            int m = m0 + wm + im * 16 + gq + h2 * 8;
            if (m < cnt) {
                int   tok = g_rowtok[e * CC + m];
                float w   = g_roww[e * CC + m];
                float* op = out + (size_t)tok * HH + n0 + wn + 2 * t;
                #pragma unroll
                for (int nt = 0; nt < 4; nt++) {
                    atomicAdd(op + nt * 8,     w * acc[im][nt][h2 * 2]);
                    atomicAdd(op + nt * 8 + 1, w * acc[im][nt][h2 * 2 + 1]);
                }
            }
        }
    }
}

// ---------------------------------------------------------------------------
extern "C" void kernel_launch(void* const* d_in, const int* in_sizes, int n_in,
                              void* d_out, int out_size)
{
    const float* x      = (const float*)d_in[0];
    const float* gw     = (const float*)d_in[1];
    const float* bias   = (const float*)d_in[2];
    const float* w_gate = (const float*)d_in[3];
    const float* w_up   = (const float*)d_in[4];
    const float* w_down = (const float*)d_in[5];
    float* out = (float*)d_out;

    cudaFuncSetAttribute(gemm1_kernel, cudaFuncAttributeMaxDynamicSharedMemorySize, 3 * G1_STG);
    cudaFuncSetAttribute(gemm2_kernel, cudaFuncAttributeMaxDynamicSharedMemorySize, 3 * G2_STG);

    __half* wgh; cudaGetSymbolAddress((void**)&wgh, g_wgh);
    __half* wuh; cudaGetSymbolAddress((void**)&wuh, g_wuh);
    __half* wdh; cudaGetSymbolAddress((void**)&wdh, g_wdh);
    __half* xh;  cudaGetSymbolAddress((void**)&xh,  g_xh);

    const size_t WN = (size_t)EE * II * HH;   // elements per weight tensor

    zero_cnt_kernel<<<1, 64>>>();
    zero_out_kernel<<<(TT * HH / 4) / 256, 256>>>((float4*)out);
    f2h_kernel<<<(int)((TT * (size_t)HH / 8) / 256), 256>>>((const float4*)x, (uint4*)xh);
    f2h_kernel<<<(int)((WN / 8) / 256), 256>>>((const float4*)w_gate, (uint4*)wgh);
    f2h_kernel<<<(int)((WN / 8) / 256), 256>>>((const float4*)w_up,   (uint4*)wuh);
    f2h_kernel<<<(int)((WN / 8) / 256), 256>>>((const float4*)w_down, (uint4*)wdh);
    logits_kernel<<<TT / 64, 256>>>(x, gw);
    topk_kernel<<<TT / 16, 512>>>(bias);
    gemm1_kernel<<<dim3(II / 128, CC / 128, EE), 256, 3 * G1_STG>>>();
    gemm2_kernel<<<dim3(HH / 128, CC / 128, EE), 256, 3 * G2_STG>>>(out);
}

// round 5
// speedup vs baseline: 5.1666x; 1.0055x over previous
#include <cuda_runtime.h>
#include <cuda_fp16.h>
#include <math.h>

#define TT 4096
#define HH 1536
#define II 768
#define EE 64
#define KK 8
#define CC 1024

// Scratch (no allocation allowed).
__device__ int    g_cnt[EE];
__device__ int    g_rowtok[EE * CC];
__device__ int    g_te[TT * KK];
__device__ int    g_tpos[TT * KK];
__device__ float  g_tw[TT * KK];
__device__ float  g_logits[(size_t)TT * EE];
__device__ __half g_xh[(size_t)TT * HH];            // fp16 hidden_states
__device__ __half g_h[(size_t)EE * CC * II];        // SwiGLU activations fp16
__device__ float  g_y[(size_t)EE * CC * HH];        // expert outputs fp32
__device__ __half g_wgh[(size_t)EE * II * HH];      // fp16 w_gate
__device__ __half g_wuh[(size_t)EE * II * HH];      // fp16 w_up
__device__ __half g_wdh[(size_t)EE * HH * II];      // fp16 w_down

// ---------------------------------------------------------------------------
// helpers
// ---------------------------------------------------------------------------
__device__ __forceinline__ void mma16(float* c, const unsigned* a, unsigned b0, unsigned b1) {
    asm volatile(
        "mma.sync.aligned.m16n8k16.row.col.f32.f16.f16.f32 "
        "{%0,%1,%2,%3}, {%4,%5,%6,%7}, {%8,%9}, {%0,%1,%2,%3};\n"
        : "+f"(c[0]), "+f"(c[1]), "+f"(c[2]), "+f"(c[3])
        : "r"(a[0]), "r"(a[1]), "r"(a[2]), "r"(a[3]), "r"(b0), "r"(b1));
}
__device__ __forceinline__ void ldsm4(unsigned& r0, unsigned& r1, unsigned& r2, unsigned& r3,
                                      unsigned addr) {
    asm volatile("ldmatrix.sync.aligned.m8n8.x4.shared.b16 {%0,%1,%2,%3}, [%4];"
                 : "=r"(r0), "=r"(r1), "=r"(r2), "=r"(r3) : "r"(addr));
}
__device__ __forceinline__ void cpa(unsigned dst, const void* src, unsigned sz) {
    asm volatile("cp.async.cg.shared.global [%0], [%1], 16, %2;\n"
                 :: "r"(dst), "l"(src), "r"(sz));
}
#define CP_COMMIT asm volatile("cp.async.commit_group;\n")
#define CP_WAIT1  asm volatile("cp.async.wait_group 1;\n")

__global__ void zero_cnt_kernel() {
    if (threadIdx.x < EE) g_cnt[threadIdx.x] = 0;
}
// generic fp32 -> fp16 (8 elements / thread)
__global__ void f2h_kernel(const float4* __restrict__ src, uint4* __restrict__ dst) {
    size_t i = (size_t)blockIdx.x * blockDim.x + threadIdx.x;
    float4 v0 = src[2 * i], v1 = src[2 * i + 1];
    __half2 h0 = __floats2half2_rn(v0.x, v0.y);
    __half2 h1 = __floats2half2_rn(v0.z, v0.w);
    __half2 h2 = __floats2half2_rn(v1.x, v1.y);
    __half2 h3 = __floats2half2_rn(v1.z, v1.w);
    uint4 o;
    o.x = *(unsigned*)&h0; o.y = *(unsigned*)&h1;
    o.z = *(unsigned*)&h2; o.w = *(unsigned*)&h3;
    dst[i] = o;
}

// ---------------------------------------------------------------------------
// Router part 1: logits = x @ gate_w^T in exact fp32.
// ---------------------------------------------------------------------------
__global__ __launch_bounds__(256) void logits_kernel(
    const float* __restrict__ x,
    const float* __restrict__ gw)
{
    __shared__ float As[16][64];
    __shared__ float Bs[16][64];

    int tid  = threadIdx.x;
    int tok0 = blockIdx.x * 64;

    int lrow = tid >> 2;
    int lkq  = (tid & 3) << 2;
    const float* ap = x  + (size_t)(tok0 + lrow) * HH + lkq;
    const float* bp = gw + (size_t)lrow * HH + lkq;

    int tx = (tid & 15) << 2;
    int ty = (tid >> 4) << 2;

    float acc[4][4] = {};

    for (int k0 = 0; k0 < HH; k0 += 16) {
        float4 av = *(const float4*)(ap + k0);
        float4 bv = *(const float4*)(bp + k0);
        __syncthreads();
        As[lkq][lrow] = av.x; As[lkq + 1][lrow] = av.y; As[lkq + 2][lrow] = av.z; As[lkq + 3][lrow] = av.w;
        Bs[lkq][lrow] = bv.x; Bs[lkq + 1][lrow] = bv.y; Bs[lkq + 2][lrow] = bv.z; Bs[lkq + 3][lrow] = bv.w;
        __syncthreads();
        #pragma unroll
        for (int k = 0; k < 16; k++) {
            float4 a = *(const float4*)&As[k][ty];
            float4 b = *(const float4*)&Bs[k][tx];
            float aa[4] = {a.x, a.y, a.z, a.w};
            float bb[4] = {b.x, b.y, b.z, b.w};
            #pragma unroll
            for (int i = 0; i < 4; i++)
                #pragma unroll
                for (int j = 0; j < 4; j++)
                    acc[i][j] = fmaf(aa[i], bb[j], acc[i][j]);
        }
    }
    #pragma unroll
    for (int i = 0; i < 4; i++)
        #pragma unroll
        for (int j = 0; j < 4; j++)
            g_logits[(size_t)(tok0 + ty + i) * EE + tx + j] = acc[i][j];
}

// ---------------------------------------------------------------------------
// Router part 2: sigmoid + bias + top-8 + atomic dispatch. Warp per token.
// Also records per-(token,k) (expert, pos, weight) for the combine pass.
// ---------------------------------------------------------------------------
__global__ __launch_bounds__(512) void topk_kernel(const float* __restrict__ bias)
{
    int warp = threadIdx.x >> 5, lane = threadIdx.x & 31;
    int tok  = blockIdx.x * 16 + warp;

    float l0 = g_logits[(size_t)tok * EE + lane];
    float l1 = g_logits[(size_t)tok * EE + lane + 32];
    float sc0 = 1.f / (1.f + expf(-l0));
    float sc1 = 1.f / (1.f + expf(-l1));
    float v0 = sc0 + bias[lane];
    float v1 = sc1 + bias[lane + 32];

    int   my_e = -1;
    float wsum = 0.f;
    #pragma unroll
    for (int k = 0; k < KK; k++) {
        float v; int id;
        if (v0 >= v1) { v = v0; id = lane; } else { v = v1; id = lane + 32; }
        #pragma unroll
        for (int off = 16; off; off >>= 1) {
            float ov = __shfl_xor_sync(0xffffffffu, v, off);
            int   oi = __shfl_xor_sync(0xffffffffu, id, off);
            if (ov > v || (ov == v && oi < id)) { v = ov; id = oi; }
        }
        float s0 = __shfl_sync(0xffffffffu, sc0, id & 31);
        float s1 = __shfl_sync(0xffffffffu, sc1, id & 31);
        wsum += (id < 32) ? s0 : s1;
        if (k == lane) my_e = id;
        if (id == lane)      v0 = -1e30f;
        if (id == lane + 32) v1 = -1e30f;
    }
    {
        int src = (my_e >= 0) ? (my_e & 31) : 0;
        float s0 = __shfl_sync(0xffffffffu, sc0, src);
        float s1 = __shfl_sync(0xffffffffu, sc1, src);
        if (lane < KK) {
            float wgt = ((my_e < 32) ? s0 : s1) / wsum;
            int pos = atomicAdd(&g_cnt[my_e], 1);
            if (pos < CC) g_rowtok[my_e * CC + pos] = tok;
            g_te[tok * KK + lane]   = my_e;
            g_tpos[tok * KK + lane] = pos;
            g_tw[tok * KK + lane]   = wgt;
        }
    }
}

// ---------------------------------------------------------------------------
// GEMM1 (fp16 mma + ldmatrix): gathered A[128 x K] x {w_gate,w_up}[256 x K],
// SiLU(g)*u -> g_h. BM=128, BN=128(x2), BK=32, 8 warps, 3-stage cp.async.
// ---------------------------------------------------------------------------
#define G1_AB   (128 * 40 * 2)
#define G1_BB   (256 * 40 * 2)
#define G1_STG  (G1_AB + G1_BB)

__global__ __launch_bounds__(256, 1) void gemm1_kernel()
{
    extern __shared__ char smem[];
    int e   = blockIdx.z;
    int cnt = min(g_cnt[e], CC);
    int m0  = blockIdx.y * 128;
    if (m0 >= cnt) return;
    int n0  = blockIdx.x * 128;

    int tid = threadIdx.x;
    unsigned sbase = (unsigned)__cvta_generic_to_shared(smem);

    const __half* aptr[2]; unsigned asz[2]; unsigned aoff[2];
    #pragma unroll
    for (int i = 0; i < 2; i++) {
        int c = tid + i * 256;
        int r = c >> 2, k8 = (c & 3) * 8;
        int m = m0 + r;
        int ok = m < cnt;
        int tok = ok ? g_rowtok[e * CC + m] : 0;
        aptr[i] = g_xh + (size_t)tok * HH + k8;
        asz[i]  = ok ? 16u : 0u;
        aoff[i] = (unsigned)(r * 40 + k8) * 2u;
    }
    const __half* bptr[4]; unsigned boff[4];
    #pragma unroll
    for (int i = 0; i < 4; i++) {
        int c = tid + i * 256;
        int r = c >> 2, k8 = (c & 3) * 8;
        const __half* base = (r < 128)
            ? g_wgh + ((size_t)e * II + n0 + r) * HH
            : g_wuh + ((size_t)e * II + n0 + (r - 128)) * HH;
        bptr[i] = base + k8;
        boff[i] = (unsigned)(G1_AB + (r * 40 + k8) * 2);
    }

    int warp = tid >> 5, lane = tid & 31;
    int wm = (warp & 1) * 64, wn = (warp >> 1) * 32;
    int gq = lane >> 2, t = lane & 3;

    unsigned a_lane = (unsigned)(((lane & 15) * 40 + (lane >> 4) * 8) * 2);
    unsigned b_lane = (unsigned)(((((lane & 7) + ((lane >> 4) & 1) * 8)) * 40
                                  + ((lane >> 3) & 1) * 8) * 2);

    float acc[2][4][4][4] = {};

    #pragma unroll
    for (int s = 0; s < 2; s++) {
        int k0 = s * 32;
        unsigned so = sbase + s * G1_STG;
        #pragma unroll
        for (int i = 0; i < 2; i++) cpa(so + aoff[i], aptr[i] + k0, asz[i]);
        #pragma unroll
        for (int i = 0; i < 4; i++) cpa(so + boff[i], bptr[i] + k0, 16);
        CP_COMMIT;
    }

    const int NK = HH / 32;
    int s = 0;
    for (int kt = 0; kt < NK; kt++) {
        CP_WAIT1;
        __syncthreads();
        if (kt + 2 < NK) {
            int k0 = (kt + 2) * 32;
            int s2 = s + 2; if (s2 >= 3) s2 -= 3;
            unsigned so = sbase + s2 * G1_STG;
            #pragma unroll
            for (int i = 0; i < 2; i++) cpa(so + aoff[i], aptr[i] + k0, asz[i]);
            #pragma unroll
            for (int i = 0; i < 4; i++) cpa(so + boff[i], bptr[i] + k0, 16);
        }
        CP_COMMIT;

        unsigned sA = sbase + s * G1_STG;
        unsigned sB = sA + G1_AB;
        #pragma unroll
        for (int ks = 0; ks < 2; ks++) {
            unsigned a[4][4];
            #pragma unroll
            for (int im = 0; im < 4; im++)
                ldsm4(a[im][0], a[im][1], a[im][2], a[im][3],
                      sA + a_lane + (unsigned)((wm + im * 16) * 80 + ks * 32));
            #pragma unroll
            for (int kind = 0; kind < 2; kind++) {
                #pragma unroll
                for (int ntp = 0; ntp < 2; ntp++) {
                    unsigned b0, b1, b2, b3;
                    ldsm4(b0, b1, b2, b3,
                          sB + b_lane + (unsigned)((kind * 128 + wn + ntp * 16) * 80 + ks * 32));
                    #pragma unroll
                    for (int im = 0; im < 4; im++) {
                        mma16(acc[kind][im][2 * ntp],     a[im], b0, b1);
                        mma16(acc[kind][im][2 * ntp + 1], a[im], b2, b3);
                    }
                }
            }
        }
        if (++s >= 3) s -= 3;
    }

    #pragma unroll
    for (int im = 0; im < 4; im++) {
        #pragma unroll
        for (int h2 = 0; h2 < 2; h2++) {
            int m = m0 + wm + im * 16 + gq + h2 * 8;
            if (m < cnt) {
                __half* dst = g_h + ((size_t)e * CC + m) * II + n0 + wn + 2 * t;
                #pragma unroll
                for (int nt = 0; nt < 4; nt++) {
                    float g0 = acc[0][im][nt][h2 * 2],     g1 = acc[0][im][nt][h2 * 2 + 1];
                    float u0 = acc[1][im][nt][h2 * 2],     u1 = acc[1][im][nt][h2 * 2 + 1];
                    float r0 = g0 * (1.f / (1.f + expf(-g0))) * u0;
                    float r1 = g1 * (1.f / (1.f + expf(-g1))) * u1;
                    *(__half2*)(dst + nt * 8) = __floats2half2_rn(r0, r1);
                }
            }
        }
    }
}

// ---------------------------------------------------------------------------
// GEMM2 (fp16 mma + ldmatrix): g_h[128 x I] x w_down[256 x I]^T -> g_y fp32.
// BM=128, BN=256, BK=32, 8 warps (2m x 4n), warp tile 64x64, plain stores.
// ---------------------------------------------------------------------------
#define G2_AB   (128 * 40 * 2)
#define G2_BB   (256 * 40 * 2)
#define G2_STG  (G2_AB + G2_BB)

__global__ __launch_bounds__(256, 1) void gemm2_kernel()
{
    extern __shared__ char smem[];
    int e   = blockIdx.z;
    int cnt = min(g_cnt[e], CC);
    int m0  = blockIdx.y * 128;
    if (m0 >= cnt) return;
    int n0  = blockIdx.x * 256;

    int tid = threadIdx.x;
    unsigned sbase = (unsigned)__cvta_generic_to_shared(smem);

    const __half* aptr[2]; unsigned aoff[2];
    #pragma unroll
    for (int i = 0; i < 2; i++) {
        int c = tid + i * 256;
        int r = c >> 2, k8 = (c & 3) * 8;
        aptr[i] = g_h + ((size_t)e * CC + m0 + r) * II + k8;   // stale rows masked in epilogue
        aoff[i] = (unsigned)(r * 40 + k8) * 2u;
    }
    const __half* bptr[4]; unsigned boff[4];
    #pragma unroll
    for (int i = 0; i < 4; i++) {
        int c = tid + i * 256;
        int r = c >> 2, k8 = (c & 3) * 8;
        bptr[i] = g_wdh + ((size_t)e * HH + n0 + r) * II + k8;
        boff[i] = (unsigned)(G2_AB + (r * 40 + k8) * 2);
    }

    int warp = tid >> 5, lane = tid & 31;
    int wm = (warp & 1) * 64, wn = (warp >> 1) * 64;
    int gq = lane >> 2, t = lane & 3;

    unsigned a_lane = (unsigned)(((lane & 15) * 40 + (lane >> 4) * 8) * 2);
    unsigned b_lane = (unsigned)(((((lane & 7) + ((lane >> 4) & 1) * 8)) * 40
                                  + ((lane >> 3) & 1) * 8) * 2);

    float acc[4][8][4] = {};

    #pragma unroll
    for (int s = 0; s < 2; s++) {
        int k0 = s * 32;
        unsigned so = sbase + s * G2_STG;
        #pragma unroll
        for (int i = 0; i < 2; i++) cpa(so + aoff[i], aptr[i] + k0, 16);
        #pragma unroll
        for (int i = 0; i < 4; i++) cpa(so + boff[i], bptr[i] + k0, 16);
        CP_COMMIT;
    }

    const int NK = II / 32;
    int s = 0;
    for (int kt = 0; kt < NK; kt++) {
        CP_WAIT1;
        __syncthreads();
        if (kt + 2 < NK) {
            int k0 = (kt + 2) * 32;
            int s2 = s + 2; if (s2 >= 3) s2 -= 3;
            unsigned so = sbase + s2 * G2_STG;
            #pragma unroll
            for (int i = 0; i < 2; i++) cpa(so + aoff[i], aptr[i] + k0, 16);
            #pragma unroll
            for (int i = 0; i < 4; i++) cpa(so + boff[i], bptr[i] + k0, 16);
        }
        CP_COMMIT;

        unsigned sA = sbase + s * G2_STG;
        unsigned sB = sA + G2_AB;
        #pragma unroll
        for (int ks = 0; ks < 2; ks++) {
            unsigned a[4][4];
            #pragma unroll
            for (int im = 0; im < 4; im++)
                ldsm4(a[im][0], a[im][1], a[im][2], a[im][3],
                      sA + a_lane + (unsigned)((wm + im * 16) * 80 + ks * 32));
            #pragma unroll
            for (int ntp = 0; ntp < 4; ntp++) {
                unsigned b0, b1, b2, b3;
                ldsm4(b0, b1, b2, b3,
                      sB + b_lane + (unsigned)((wn + ntp * 16) * 80 + ks * 32));
                #pragma unroll
                for (int im = 0; im < 4; im++) {
                    mma16(acc[im][2 * ntp],     a[im], b0, b1);
                    mma16(acc[im][2 * ntp + 1], a[im], b2, b3);
                }
            }
        }
        if (++s >= 3) s -= 3;
    }

    #pragma unroll
    for (int im = 0; im < 4; im++) {
        #pragma unroll
        for (int h2 = 0; h2 < 2; h2++) {
            int m = m0 + wm + im * 16 + gq + h2 * 8;
            if (m < cnt) {
                float* dst = g_y + ((size_t)e * CC + m) * HH + n0 + wn + 2 * t;
                #pragma unroll
                for (int nt = 0; nt < 8; nt++)
                    *(float2*)(dst + nt * 8) =
                        make_float2(acc[im][nt][h2 * 2], acc[im][nt][h2 * 2 + 1]);
            }
        }
    }
}

// ---------------------------------------------------------------------------
// Combine: out[tok] = sum_k w[k] * g_y[e_k, pos_k]  (block per token)
// ---------------------------------------------------------------------------
__global__ __launch_bounds__(128) void combine_kernel(float* __restrict__ out)
{
    int tok = blockIdx.x;
    int tid = threadIdx.x;

    __shared__ const float* srow[KK];
    __shared__ float swk[KK];
    if (tid < KK) {
        int e   = g_te[tok * KK + tid];
        int p   = g_tpos[tok * KK + tid];
        srow[tid] = (p < CC) ? (g_y + ((size_t)e * CC + p) * HH) : (const float*)0;
        swk[tid]  = g_tw[tok * KK + tid];
    }
    __syncthreads();

    const float* r[KK]; float w[KK];
    #pragma unroll
    for (int k = 0; k < KK; k++) { r[k] = srow[k]; w[k] = swk[k]; }

    #pragma unroll
    for (int j = 0; j < HH / 2 / 128; j++) {
        int c = tid + j * 128;          // float2 index
        float2 acc = make_float2(0.f, 0.f);
        #pragma unroll
        for (int k = 0; k < KK; k++) {
            if (r[k]) {
                float2 v = *(const float2*)(r[k] + 2 * c);
                acc.x = fmaf(w[k], v.x, acc.x);
                acc.y = fmaf(w[k], v.y, acc.y);
            }
        }
        *(float2*)(out + (size_t)tok * HH + 2 * c) = acc;
    }
}

// ---------------------------------------------------------------------------
extern "C" void kernel_launch(void* const* d_in, const int* in_sizes, int n_in,
                              void* d_out, int out_size)
{
    const float* x      = (const float*)d_in[0];
    const float* gw     = (const float*)d_in[1];
    const float* bias   = (const float*)d_in[2];
    const float* w_gate = (const float*)d_in[3];
    const float* w_up   = (const float*)d_in[4];
    const float* w_down = (const float*)d_in[5];
    float* out = (float*)d_out;

    cudaFuncSetAttribute(gemm1_kernel, cudaFuncAttributeMaxDynamicSharedMemorySize, 3 * G1_STG);
    cudaFuncSetAttribute(gemm2_kernel, cudaFuncAttributeMaxDynamicSharedMemorySize, 3 * G2_STG);

    __half* wgh; cudaGetSymbolAddress((void**)&wgh, g_wgh);
    __half* wuh; cudaGetSymbolAddress((void**)&wuh, g_wuh);
    __half* wdh; cudaGetSymbolAddress((void**)&wdh, g_wdh);
    __half* xh;  cudaGetSymbolAddress((void**)&xh,  g_xh);

    const size_t WN = (size_t)EE * II * HH;

    zero_cnt_kernel<<<1, 64>>>();
    f2h_kernel<<<(int)((TT * (size_t)HH / 8) / 256), 256>>>((const float4*)x, (uint4*)xh);
    f2h_kernel<<<(int)((WN / 8) / 256), 256>>>((const float4*)w_gate, (uint4*)wgh);
    f2h_kernel<<<(int)((WN / 8) / 256), 256>>>((const float4*)w_up,   (uint4*)wuh);
    f2h_kernel<<<(int)((WN / 8) / 256), 256>>>((const float4*)w_down, (uint4*)wdh);
    logits_kernel<<<TT / 64, 256>>>(x, gw);
    topk_kernel<<<TT / 16, 512>>>(bias);
    gemm1_kernel<<<dim3(II / 128, CC / 128, EE), 256, 3 * G1_STG>>>();
    gemm2_kernel<<<dim3(HH / 256, CC / 128, EE), 256, 3 * G2_STG>>>();
    combine_kernel<<<TT, 128>>>(out);
}

// round 7
// speedup vs baseline: 5.6107x; 1.0859x over previous
#include <cuda_runtime.h>
#include <cuda_fp16.h>
#include <math.h>

#define TT 4096
#define HH 1536
#define II 768
#define EE 64
#define KK 8
#define CC 1024

// Scratch (no allocation allowed).
__device__ int    g_cnt[EE];
__device__ int    g_rowtok[EE * CC];
__device__ int    g_te[TT * KK];
__device__ int    g_tpos[TT * KK];
__device__ float  g_tw[TT * KK];
__device__ float  g_logits[(size_t)TT * EE];
__device__ __half g_xh[(size_t)TT * HH];            // fp16 hidden_states
__device__ __half g_h[(size_t)EE * CC * II];        // SwiGLU activations fp16
__device__ __half g_y[(size_t)EE * CC * HH];        // expert outputs fp16
__device__ __half g_wgh[(size_t)EE * II * HH];      // fp16 w_gate
__device__ __half g_wuh[(size_t)EE * II * HH];      // fp16 w_up
__device__ __half g_wdh[(size_t)EE * HH * II];      // fp16 w_down

// ---------------------------------------------------------------------------
// helpers
// ---------------------------------------------------------------------------
__device__ __forceinline__ void mma16(float* c, const unsigned* a, unsigned b0, unsigned b1) {
    asm volatile(
        "mma.sync.aligned.m16n8k16.row.col.f32.f16.f16.f32 "
        "{%0,%1,%2,%3}, {%4,%5,%6,%7}, {%8,%9}, {%0,%1,%2,%3};\n"
        : "+f"(c[0]), "+f"(c[1]), "+f"(c[2]), "+f"(c[3])
        : "r"(a[0]), "r"(a[1]), "r"(a[2]), "r"(a[3]), "r"(b0), "r"(b1));
}
__device__ __forceinline__ void ldsm4(unsigned& r0, unsigned& r1, unsigned& r2, unsigned& r3,
                                      unsigned addr) {
    asm volatile("ldmatrix.sync.aligned.m8n8.x4.shared.b16 {%0,%1,%2,%3}, [%4];"
                 : "=r"(r0), "=r"(r1), "=r"(r2), "=r"(r3) : "r"(addr));
}
__device__ __forceinline__ void cpa(unsigned dst, const void* src, unsigned sz) {
    asm volatile("cp.async.cg.shared.global [%0], [%1], 16, %2;\n"
                 :: "r"(dst), "l"(src), "r"(sz));
}
#define CP_COMMIT asm volatile("cp.async.commit_group;\n")
#define CP_WAIT1  asm volatile("cp.async.wait_group 1;\n")

__device__ __forceinline__ void conv8(const float4* __restrict__ src, uint4* __restrict__ dst,
                                      size_t i) {
    float4 v0 = src[2 * i], v1 = src[2 * i + 1];
    __half2 h0 = __floats2half2_rn(v0.x, v0.y);
    __half2 h1 = __floats2half2_rn(v0.z, v0.w);
    __half2 h2 = __floats2half2_rn(v1.x, v1.y);
    __half2 h3 = __floats2half2_rn(v1.z, v1.w);
    uint4 o;
    o.x = *(unsigned*)&h0; o.y = *(unsigned*)&h1;
    o.z = *(unsigned*)&h2; o.w = *(unsigned*)&h3;
    dst[i] = o;
}

// ---------------------------------------------------------------------------
// K1: fused [logits (blocks 0..63)] + [fp16 conversion of x, w_gate, w_up
// (grid-stride, blocks 64..64+NC1)] + cnt zeroing. Overlaps DRAM-bound
// conversion with compute-bound logits GEMM in one launch.
// ---------------------------------------------------------------------------
#define NC1 1536

__global__ __launch_bounds__(256) void k1_kernel(
    const float* __restrict__ x,
    const float* __restrict__ gw,
    const float4* __restrict__ wg32,
    const float4* __restrict__ wu32)
{
    int bx  = blockIdx.x;
    int tid = threadIdx.x;

    if (bx >= 64) {
        // converter branch: x (XCH chunks), then w_gate, then w_up
        const size_t XCH = (size_t)TT * HH / 8;
        const size_t WCH = (size_t)EE * II * HH / 8;
        const size_t total = XCH + 2 * WCH;
        size_t idx = (size_t)(bx - 64) * 256 + tid;
        for (size_t i = idx; i < total; i += (size_t)NC1 * 256) {
            if (i < XCH)            conv8((const float4*)x, (uint4*)g_xh, i);
            else if (i < XCH + WCH) conv8(wg32, (uint4*)g_wgh, i - XCH);
            else                    conv8(wu32, (uint4*)g_wuh, i - XCH - WCH);
        }
        return;
    }

    if (bx == 0 && tid < EE) g_cnt[tid] = 0;

    __shared__ float As[16][64];
    __shared__ float Bs[16][64];

    int tok0 = bx * 64;
    int lrow = tid >> 2;
    int lkq  = (tid & 3) << 2;
    const float* ap = x  + (size_t)(tok0 + lrow) * HH + lkq;
    const float* bp = gw + (size_t)lrow * HH + lkq;
    int tx = (tid & 15) << 2;
    int ty = (tid >> 4) << 2;
    float acc[4][4] = {};

    for (int k0 = 0; k0 < HH; k0 += 16) {
        float4 av = *(const float4*)(ap + k0);
        float4 bv = *(const float4*)(bp + k0);
        __syncthreads();
        As[lkq][lrow] = av.x; As[lkq + 1][lrow] = av.y; As[lkq + 2][lrow] = av.z; As[lkq + 3][lrow] = av.w;
        Bs[lkq][lrow] = bv.x; Bs[lkq + 1][lrow] = bv.y; Bs[lkq + 2][lrow] = bv.z; Bs[lkq + 3][lrow] = bv.w;
        __syncthreads();
        #pragma unroll
        for (int k = 0; k < 16; k++) {
            float4 a = *(const float4*)&As[k][ty];
            float4 b = *(const float4*)&Bs[k][tx];
            float aa[4] = {a.x, a.y, a.z, a.w};
            float bb[4] = {b.x, b.y, b.z, b.w};
            #pragma unroll
            for (int i = 0; i < 4; i++)
                #pragma unroll
                for (int j = 0; j < 4; j++)
                    acc[i][j] = fmaf(aa[i], bb[j], acc[i][j]);
        }
    }
    #pragma unroll
    for (int i = 0; i < 4; i++)
        #pragma unroll
        for (int j = 0; j < 4; j++)
            g_logits[(size_t)(tok0 + ty + i) * EE + tx + j] = acc[i][j];
}

// ---------------------------------------------------------------------------
// Router part 2: sigmoid + bias + top-8 + atomic dispatch. Warp per token.
// ---------------------------------------------------------------------------
__global__ __launch_bounds__(512) void topk_kernel(const float* __restrict__ bias)
{
    int warp = threadIdx.x >> 5, lane = threadIdx.x & 31;
    int tok  = blockIdx.x * 16 + warp;

    float l0 = g_logits[(size_t)tok * EE + lane];
    float l1 = g_logits[(size_t)tok * EE + lane + 32];
    float sc0 = 1.f / (1.f + expf(-l0));
    float sc1 = 1.f / (1.f + expf(-l1));
    float v0 = sc0 + bias[lane];
    float v1 = sc1 + bias[lane + 32];

    int   my_e = -1;
    float wsum = 0.f;
    #pragma unroll
    for (int k = 0; k < KK; k++) {
        float v; int id;
        if (v0 >= v1) { v = v0; id = lane; } else { v = v1; id = lane + 32; }
        #pragma unroll
        for (int off = 16; off; off >>= 1) {
            float ov = __shfl_xor_sync(0xffffffffu, v, off);
            int   oi = __shfl_xor_sync(0xffffffffu, id, off);
            if (ov > v || (ov == v && oi < id)) { v = ov; id = oi; }
        }
        float s0 = __shfl_sync(0xffffffffu, sc0, id & 31);
        float s1 = __shfl_sync(0xffffffffu, sc1, id & 31);
        wsum += (id < 32) ? s0 : s1;
        if (k == lane) my_e = id;
        if (id == lane)      v0 = -1e30f;
        if (id == lane + 32) v1 = -1e30f;
    }
    {
        int src = (my_e >= 0) ? (my_e & 31) : 0;
        float s0 = __shfl_sync(0xffffffffu, sc0, src);
        float s1 = __shfl_sync(0xffffffffu, sc1, src);
        if (lane < KK) {
            float wgt = ((my_e < 32) ? s0 : s1) / wsum;
            int pos = atomicAdd(&g_cnt[my_e], 1);
            if (pos < CC) g_rowtok[my_e * CC + pos] = tok;
            g_te[tok * KK + lane]   = my_e;
            g_tpos[tok * KK + lane] = pos;
            g_tw[tok * KK + lane]   = wgt;
        }
    }
}

// ---------------------------------------------------------------------------
// GEMM1 (fp16 mma + ldmatrix): gathered A[128 x K] x {w_gate,w_up}[256 x K],
// SiLU(g)*u -> g_h. BM=128, BN=128(x2), BK=32, 8 warps, 3-stage cp.async.
// z-slices [EE, EE+4): grid-stride fp16 conversion of w_down (hidden under
// the GEMM; gemm2 only launches after this kernel completes).
// ---------------------------------------------------------------------------
#define G1_AB   (128 * 40 * 2)
#define G1_BB   (256 * 40 * 2)
#define G1_STG  (G1_AB + G1_BB)
#define NCD     192   // w_down converter blocks (4 z-slices x 48)

__global__ __launch_bounds__(256, 1) void gemm1_kernel(const float4* __restrict__ wd32)
{
    extern __shared__ char smem[];
    int e   = blockIdx.z;
    int tid = threadIdx.x;

    if (e >= EE) {
        // w_down fp16 conversion, grid-stride over 192 blocks
        int rank = (e - EE) * 48 + blockIdx.y * 6 + blockIdx.x;
        const size_t WCH = (size_t)EE * HH * II / 8;
        for (size_t i = (size_t)rank * 256 + tid; i < WCH; i += (size_t)NCD * 256)
            conv8(wd32, (uint4*)g_wdh, i);
        return;
    }

    int cnt = min(g_cnt[e], CC);
    int m0  = blockIdx.y * 128;
    if (m0 >= cnt) return;
    int n0  = blockIdx.x * 128;

    unsigned sbase = (unsigned)__cvta_generic_to_shared(smem);

    const __half* aptr[2]; unsigned asz[2]; unsigned aoff[2];
    #pragma unroll
    for (int i = 0; i < 2; i++) {
        int c = tid + i * 256;
        int r = c >> 2, k8 = (c & 3) * 8;
        int m = m0 + r;
        int ok = m < cnt;
        int tok = ok ? g_rowtok[e * CC + m] : 0;
        aptr[i] = g_xh + (size_t)tok * HH + k8;
        asz[i]  = ok ? 16u : 0u;
        aoff[i] = (unsigned)(r * 40 + k8) * 2u;
    }
    const __half* bptr[4]; unsigned boff[4];
    #pragma unroll
    for (int i = 0; i < 4; i++) {
        int c = tid + i * 256;
        int r = c >> 2, k8 = (c & 3) * 8;
        const __half* base = (r < 128)
            ? g_wgh + ((size_t)e * II + n0 + r) * HH
            : g_wuh + ((size_t)e * II + n0 + (r - 128)) * HH;
        bptr[i] = base + k8;
        boff[i] = (unsigned)(G1_AB + (r * 40 + k8) * 2);
    }

    int warp = tid >> 5, lane = tid & 31;
    int wm = (warp & 1) * 64, wn = (warp >> 1) * 32;
    int gq = lane >> 2, t = lane & 3;

    unsigned a_lane = (unsigned)(((lane & 15) * 40 + (lane >> 4) * 8) * 2);
    unsigned b_lane = (unsigned)(((((lane & 7) + ((lane >> 4) & 1) * 8)) * 40
                                  + ((lane >> 3) & 1) * 8) * 2);

    float acc[2][4][4][4] = {};

    #pragma unroll
    for (int s = 0; s < 2; s++) {
        int k0 = s * 32;
        unsigned so = sbase + s * G1_STG;
        #pragma unroll
        for (int i = 0; i < 2; i++) cpa(so + aoff[i], aptr[i] + k0, asz[i]);
        #pragma unroll
        for (int i = 0; i < 4; i++) cpa(so + boff[i], bptr[i] + k0, 16);
        CP_COMMIT;
    }

    const int NK = HH / 32;
    int s = 0;
    for (int kt = 0; kt < NK; kt++) {
        CP_WAIT1;
        __syncthreads();
        if (kt + 2 < NK) {
            int k0 = (kt + 2) * 32;
            int s2 = s + 2; if (s2 >= 3) s2 -= 3;
            unsigned so = sbase + s2 * G1_STG;
            #pragma unroll
            for (int i = 0; i < 2; i++) cpa(so + aoff[i], aptr[i] + k0, asz[i]);
            #pragma unroll
            for (int i = 0; i < 4; i++) cpa(so + boff[i], bptr[i] + k0, 16);
        }
        CP_COMMIT;

        unsigned sA = sbase + s * G1_STG;
        unsigned sB = sA + G1_AB;
        #pragma unroll
        for (int ks = 0; ks < 2; ks++) {
            unsigned a[4][4];
            #pragma unroll
            for (int im = 0; im < 4; im++)
                ldsm4(a[im][0], a[im][1], a[im][2], a[im][3],
                      sA + a_lane + (unsigned)((wm + im * 16) * 80 + ks * 32));
            #pragma unroll
            for (int kind = 0; kind < 2; kind++) {
                #pragma unroll
                for (int ntp = 0; ntp < 2; ntp++) {
                    unsigned b0, b1, b2, b3;
                    ldsm4(b0, b1, b2, b3,
                          sB + b_lane + (unsigned)((kind * 128 + wn + ntp * 16) * 80 + ks * 32));
                    #pragma unroll
                    for (int im = 0; im < 4; im++) {
                        mma16(acc[kind][im][2 * ntp],     a[im], b0, b1);
                        mma16(acc[kind][im][2 * ntp + 1], a[im], b2, b3);
                    }
                }
            }
        }
        if (++s >= 3) s -= 3;
    }

    #pragma unroll
    for (int im = 0; im < 4; im++) {
        #pragma unroll
        for (int h2 = 0; h2 < 2; h2++) {
            int m = m0 + wm + im * 16 + gq + h2 * 8;
            if (m < cnt) {
                __half* dst = g_h + ((size_t)e * CC + m) * II + n0 + wn + 2 * t;
                #pragma unroll
                for (int nt = 0; nt < 4; nt++) {
                    float g0 = acc[0][im][nt][h2 * 2],     g1 = acc[0][im][nt][h2 * 2 + 1];
                    float u0 = acc[1][im][nt][h2 * 2],     u1 = acc[1][im][nt][h2 * 2 + 1];
                    float r0 = g0 * (1.f / (1.f + expf(-g0))) * u0;
                    float r1 = g1 * (1.f / (1.f + expf(-g1))) * u1;
                    *(__half2*)(dst + nt * 8) = __floats2half2_rn(r0, r1);
                }
            }
        }
    }
}

// ---------------------------------------------------------------------------
// GEMM2 (fp16 mma + ldmatrix): g_h[128 x I] x w_down[256 x I]^T -> g_y fp16.
// BM=128, BN=256, BK=32, 8 warps (2m x 4n), warp tile 64x64, plain stores.
// ---------------------------------------------------------------------------
#define G2_AB   (128 * 40 * 2)
#define G2_BB   (256 * 40 * 2)
#define G2_STG  (G2_AB + G2_BB)

__global__ __launch_bounds__(256, 1) void gemm2_kernel()
{
    extern __shared__ char smem[];
    int e   = blockIdx.z;
    int cnt = min(g_cnt[e], CC);
    int m0  = blockIdx.y * 128;
    if (m0 >= cnt) return;
    int n0  = blockIdx.x * 256;

    int tid = threadIdx.x;
    unsigned sbase = (unsigned)__cvta_generic_to_shared(smem);

    const __half* aptr[2]; unsigned aoff[2];
    #pragma unroll
    for (int i = 0; i < 2; i++) {
        int c = tid + i * 256;
        int r = c >> 2, k8 = (c & 3) * 8;
        aptr[i] = g_h + ((size_t)e * CC + m0 + r) * II + k8;   // stale rows masked in epilogue
        aoff[i] = (unsigned)(r * 40 + k8) * 2u;
    }
    const __half* bptr[4]; unsigned boff[4];
    #pragma unroll
    for (int i = 0; i < 4; i++) {
        int c = tid + i * 256;
        int r = c >> 2, k8 = (c & 3) * 8;
        bptr[i] = g_wdh + ((size_t)e * HH + n0 + r) * II + k8;
        boff[i] = (unsigned)(G2_AB + (r * 40 + k8) * 2);
    }

    int warp = tid >> 5, lane = tid & 31;
    int wm = (warp & 1) * 64, wn = (warp >> 1) * 64;
    int gq = lane >> 2, t = lane & 3;

    unsigned a_lane = (unsigned)(((lane & 15) * 40 + (lane >> 4) * 8) * 2);
    unsigned b_lane = (unsigned)(((((lane & 7) + ((lane >> 4) & 1) * 8)) * 40
                                  + ((lane >> 3) & 1) * 8) * 2);

    float acc[4][8][4] = {};

    #pragma unroll
    for (int s = 0; s < 2; s++) {
        int k0 = s * 32;
        unsigned so = sbase + s * G2_STG;
        #pragma unroll
        for (int i = 0; i < 2; i++) cpa(so + aoff[i], aptr[i] + k0, 16);
        #pragma unroll
        for (int i = 0; i < 4; i++) cpa(so + boff[i], bptr[i] + k0, 16);
        CP_COMMIT;
    }

    const int NK = II / 32;
    int s = 0;
    for (int kt = 0; kt < NK; kt++) {
        CP_WAIT1;
        __syncthreads();
        if (kt + 2 < NK) {
            int k0 = (kt + 2) * 32;
            int s2 = s + 2; if (s2 >= 3) s2 -= 3;
            unsigned so = sbase + s2 * G2_STG;
            #pragma unroll
            for (int i = 0; i < 2; i++) cpa(so + aoff[i], aptr[i] + k0, 16);
            #pragma unroll
            for (int i = 0; i < 4; i++) cpa(so + boff[i], bptr[i] + k0, 16);
        }
        CP_COMMIT;

        unsigned sA = sbase + s * G2_STG;
        unsigned sB = sA + G2_AB;
        #pragma unroll
        for (int ks = 0; ks < 2; ks++) {
            unsigned a[4][4];
            #pragma unroll
            for (int im = 0; im < 4; im++)
                ldsm4(a[im][0], a[im][1], a[im][2], a[im][3],
                      sA + a_lane + (unsigned)((wm + im * 16) * 80 + ks * 32));
            #pragma unroll
            for (int ntp = 0; ntp < 4; ntp++) {
                unsigned b0, b1, b2, b3;
                ldsm4(b0, b1, b2, b3,
                      sB + b_lane + (unsigned)((wn + ntp * 16) * 80 + ks * 32));
                #pragma unroll
                for (int im = 0; im < 4; im++) {
                    mma16(acc[im][2 * ntp],     a[im], b0, b1);
                    mma16(acc[im][2 * ntp + 1], a[im], b2, b3);
                }
            }
        }
        if (++s >= 3) s -= 3;
    }

    #pragma unroll
    for (int im = 0; im < 4; im++) {
        #pragma unroll
        for (int h2 = 0; h2 < 2; h2++) {
            int m = m0 + wm + im * 16 + gq + h2 * 8;
            if (m < cnt) {
                __half* dst = g_y + ((size_t)e * CC + m) * HH + n0 + wn + 2 * t;
                #pragma unroll
                for (int nt = 0; nt < 8; nt++)
                    *(__half2*)(dst + nt * 8) =
                        __floats2half2_rn(acc[im][nt][h2 * 2], acc[im][nt][h2 * 2 + 1]);
            }
        }
    }
}

// ---------------------------------------------------------------------------
// Combine: out[tok] = sum_k w[k] * g_y[e_k, pos_k]  (block per token)
// ---------------------------------------------------------------------------
__global__ __launch_bounds__(128) void combine_kernel(float* __restrict__ out)
{
    int tok = blockIdx.x;
    int tid = threadIdx.x;

    __shared__ const __half* srow[KK];
    __shared__ float swk[KK];
    if (tid < KK) {
        int e = g_te[tok * KK + tid];
        int p = g_tpos[tok * KK + tid];
        srow[tid] = (p < CC) ? (g_y + ((size_t)e * CC + p) * HH) : (const __half*)0;
        swk[tid]  = g_tw[tok * KK + tid];
    }
    __syncthreads();

    const __half* r[KK]; float w[KK];
    #pragma unroll
    for (int k = 0; k < KK; k++) { r[k] = srow[k]; w[k] = swk[k]; }

    #pragma unroll
    for (int j = 0; j < HH / 2 / 128; j++) {
        int c = tid + j * 128;
        float2 acc = make_float2(0.f, 0.f);
        #pragma unroll
        for (int k = 0; k < KK; k++) {
            if (r[k]) {
                __half2 hv = *(const __half2*)(r[k] + 2 * c);
                float2 v = __half22float2(hv);
                acc.x = fmaf(w[k], v.x, acc.x);
                acc.y = fmaf(w[k], v.y, acc.y);
            }
        }
        *(float2*)(out + (size_t)tok * HH + 2 * c) = acc;
    }
}

// ---------------------------------------------------------------------------
extern "C" void kernel_launch(void* const* d_in, const int* in_sizes, int n_in,
                              void* d_out, int out_size)
{
    const float* x      = (const float*)d_in[0];
    const float* gw     = (const float*)d_in[1];
    const float* bias   = (const float*)d_in[2];
    const float* w_gate = (const float*)d_in[3];
    const float* w_up   = (const float*)d_in[4];
    const float* w_down = (const float*)d_in[5];
    float* out = (float*)d_out;

    cudaFuncSetAttribute(gemm1_kernel, cudaFuncAttributeMaxDynamicSharedMemorySize, 3 * G1_STG);
    cudaFuncSetAttribute(gemm2_kernel, cudaFuncAttributeMaxDynamicSharedMemorySize, 3 * G2_STG);

    k1_kernel<<<64 + NC1, 256>>>(x, gw, (const float4*)w_gate, (const float4*)w_up);
    topk_kernel<<<TT / 16, 512>>>(bias);
    gemm1_kernel<<<dim3(II / 128, CC / 128, EE + 4), 256, 3 * G1_STG>>>((const float4*)w_down);
    gemm2_kernel<<<dim3(HH / 256, CC / 128, EE), 256, 3 * G2_STG>>>();
    combine_kernel<<<TT, 128>>>(out);
}

// round 8
// speedup vs baseline: 6.3112x; 1.1249x over previous
#include <cuda_runtime.h>
#include <cuda_fp16.h>
#include <math.h>

#define TT 4096
#define HH 1536
#define II 768
#define EE 64
#define KK 8
#define CC 1024

// Scratch (no allocation allowed).
__device__ int    g_cnt[EE];
__device__ int    g_rowtok[EE * CC];
__device__ int    g_te[TT * KK];
__device__ int    g_tpos[TT * KK];
__device__ float  g_tw[TT * KK];
__device__ float  g_logits[(size_t)TT * EE];
__device__ __half g_xh[(size_t)TT * HH];            // fp16 hidden_states
__device__ __half g_h[(size_t)EE * CC * II];        // SwiGLU activations fp16
__device__ __half g_y[(size_t)EE * CC * HH];        // expert outputs fp16
__device__ __half g_wgh[(size_t)EE * II * HH];      // fp16 w_gate
__device__ __half g_wuh[(size_t)EE * II * HH];      // fp16 w_up
__device__ __half g_wdh[(size_t)EE * HH * II];      // fp16 w_down

// ---------------------------------------------------------------------------
// helpers
// ---------------------------------------------------------------------------
__device__ __forceinline__ void mma16(float* c, const unsigned* a, unsigned b0, unsigned b1) {
    asm volatile(
        "mma.sync.aligned.m16n8k16.row.col.f32.f16.f16.f32 "
        "{%0,%1,%2,%3}, {%4,%5,%6,%7}, {%8,%9}, {%0,%1,%2,%3};\n"
        : "+f"(c[0]), "+f"(c[1]), "+f"(c[2]), "+f"(c[3])
        : "r"(a[0]), "r"(a[1]), "r"(a[2]), "r"(a[3]), "r"(b0), "r"(b1));
}
__device__ __forceinline__ void ldsm4(unsigned& r0, unsigned& r1, unsigned& r2, unsigned& r3,
                                      unsigned addr) {
    asm volatile("ldmatrix.sync.aligned.m8n8.x4.shared.b16 {%0,%1,%2,%3}, [%4];"
                 : "=r"(r0), "=r"(r1), "=r"(r2), "=r"(r3) : "r"(addr));
}
__device__ __forceinline__ void cpa(unsigned dst, const void* src, unsigned sz) {
    asm volatile("cp.async.cg.shared.global [%0], [%1], 16, %2;\n"
                 :: "r"(dst), "l"(src), "r"(sz));
}
#define CP_COMMIT asm volatile("cp.async.commit_group;\n")
#define CP_WAIT1  asm volatile("cp.async.wait_group 1;\n")

__device__ __forceinline__ void conv8(const float4* __restrict__ src, uint4* __restrict__ dst,
                                      size_t i) {
    float4 v0 = src[2 * i], v1 = src[2 * i + 1];
    __half2 h0 = __floats2half2_rn(v0.x, v0.y);
    __half2 h1 = __floats2half2_rn(v0.z, v0.w);
    __half2 h2 = __floats2half2_rn(v1.x, v1.y);
    __half2 h3 = __floats2half2_rn(v1.z, v1.w);
    uint4 o;
    o.x = *(unsigned*)&h0; o.y = *(unsigned*)&h1;
    o.z = *(unsigned*)&h2; o.w = *(unsigned*)&h3;
    dst[i] = o;
}

// ---------------------------------------------------------------------------
// K1: fused [logits (blocks 0..63)] + [fp16 conversion of x, w_gate, w_up] +
// cnt zeroing.
// ---------------------------------------------------------------------------
#define NC1 1536

__global__ __launch_bounds__(256) void k1_kernel(
    const float* __restrict__ x,
    const float* __restrict__ gw,
    const float4* __restrict__ wg32,
    const float4* __restrict__ wu32)
{
    int bx  = blockIdx.x;
    int tid = threadIdx.x;

    if (bx >= 64) {
        const size_t XCH = (size_t)TT * HH / 8;
        const size_t WCH = (size_t)EE * II * HH / 8;
        const size_t total = XCH + 2 * WCH;
        size_t idx = (size_t)(bx - 64) * 256 + tid;
        for (size_t i = idx; i < total; i += (size_t)NC1 * 256) {
            if (i < XCH)            conv8((const float4*)x, (uint4*)g_xh, i);
            else if (i < XCH + WCH) conv8(wg32, (uint4*)g_wgh, i - XCH);
            else                    conv8(wu32, (uint4*)g_wuh, i - XCH - WCH);
        }
        return;
    }

    if (bx == 0 && tid < EE) g_cnt[tid] = 0;

    __shared__ float As[16][64];
    __shared__ float Bs[16][64];

    int tok0 = bx * 64;
    int lrow = tid >> 2;
    int lkq  = (tid & 3) << 2;
    const float* ap = x  + (size_t)(tok0 + lrow) * HH + lkq;
    const float* bp = gw + (size_t)lrow * HH + lkq;
    int tx = (tid & 15) << 2;
    int ty = (tid >> 4) << 2;
    float acc[4][4] = {};

    for (int k0 = 0; k0 < HH; k0 += 16) {
        float4 av = *(const float4*)(ap + k0);
        float4 bv = *(const float4*)(bp + k0);
        __syncthreads();
        As[lkq][lrow] = av.x; As[lkq + 1][lrow] = av.y; As[lkq + 2][lrow] = av.z; As[lkq + 3][lrow] = av.w;
        Bs[lkq][lrow] = bv.x; Bs[lkq + 1][lrow] = bv.y; Bs[lkq + 2][lrow] = bv.z; Bs[lkq + 3][lrow] = bv.w;
        __syncthreads();
        #pragma unroll
        for (int k = 0; k < 16; k++) {
            float4 a = *(const float4*)&As[k][ty];
            float4 b = *(const float4*)&Bs[k][tx];
            float aa[4] = {a.x, a.y, a.z, a.w};
            float bb[4] = {b.x, b.y, b.z, b.w};
            #pragma unroll
            for (int i = 0; i < 4; i++)
                #pragma unroll
                for (int j = 0; j < 4; j++)
                    acc[i][j] = fmaf(aa[i], bb[j], acc[i][j]);
        }
    }
    #pragma unroll
    for (int i = 0; i < 4; i++)
        #pragma unroll
        for (int j = 0; j < 4; j++)
            g_logits[(size_t)(tok0 + ty + i) * EE + tx + j] = acc[i][j];
}

// ---------------------------------------------------------------------------
// Router part 2: sigmoid + bias + top-8 + atomic dispatch. Warp per token.
// ---------------------------------------------------------------------------
__global__ __launch_bounds__(512) void topk_kernel(const float* __restrict__ bias)
{
    int warp = threadIdx.x >> 5, lane = threadIdx.x & 31;
    int tok  = blockIdx.x * 16 + warp;

    float l0 = g_logits[(size_t)tok * EE + lane];
    float l1 = g_logits[(size_t)tok * EE + lane + 32];
    float sc0 = 1.f / (1.f + expf(-l0));
    float sc1 = 1.f / (1.f + expf(-l1));
    float v0 = sc0 + bias[lane];
    float v1 = sc1 + bias[lane + 32];

    int   my_e = -1;
    float wsum = 0.f;
    #pragma unroll
    for (int k = 0; k < KK; k++) {
        float v; int id;
        if (v0 >= v1) { v = v0; id = lane; } else { v = v1; id = lane + 32; }
        #pragma unroll
        for (int off = 16; off; off >>= 1) {
            float ov = __shfl_xor_sync(0xffffffffu, v, off);
            int   oi = __shfl_xor_sync(0xffffffffu, id, off);
            if (ov > v || (ov == v && oi < id)) { v = ov; id = oi; }
        }
        float s0 = __shfl_sync(0xffffffffu, sc0, id & 31);
        float s1 = __shfl_sync(0xffffffffu, sc1, id & 31);
        wsum += (id < 32) ? s0 : s1;
        if (k == lane) my_e = id;
        if (id == lane)      v0 = -1e30f;
        if (id == lane + 32) v1 = -1e30f;
    }
    {
        int src = (my_e >= 0) ? (my_e & 31) : 0;
        float s0 = __shfl_sync(0xffffffffu, sc0, src);
        float s1 = __shfl_sync(0xffffffffu, sc1, src);
        if (lane < KK) {
            float wgt = ((my_e < 32) ? s0 : s1) / wsum;
            int pos = atomicAdd(&g_cnt[my_e], 1);
            if (pos < CC) g_rowtok[my_e * CC + pos] = tok;
            g_te[tok * KK + lane]   = my_e;
            g_tpos[tok * KK + lane] = pos;
            g_tw[tok * KK + lane]   = wgt;
        }
    }
}

// ---------------------------------------------------------------------------
// GEMM1: 512 threads, 16 warps (4m x 4n), warp tile 32m x 32n per kind.
// BM=128, BN=128(x2 kinds), BK=32, 3-stage cp.async.
// z-slices [EE, EE+4): w_down fp16 conversion (hidden under the GEMM).
// ---------------------------------------------------------------------------
#define G1_AB   (128 * 40 * 2)
#define G1_BB   (256 * 40 * 2)
#define G1_STG  (G1_AB + G1_BB)
#define NCD     192

__global__ __launch_bounds__(512, 1) void gemm1_kernel(const float4* __restrict__ wd32)
{
    extern __shared__ char smem[];
    int e   = blockIdx.z;
    int tid = threadIdx.x;

    if (e >= EE) {
        int rank = (e - EE) * 48 + blockIdx.y * 6 + blockIdx.x;
        const size_t WCH = (size_t)EE * HH * II / 8;
        for (size_t i = (size_t)rank * 512 + tid; i < WCH; i += (size_t)NCD * 512)
            conv8(wd32, (uint4*)g_wdh, i);
        return;
    }

    int cnt = min(g_cnt[e], CC);
    int m0  = blockIdx.y * 128;
    if (m0 >= cnt) return;
    int n0  = blockIdx.x * 128;

    unsigned sbase = (unsigned)__cvta_generic_to_shared(smem);

    // A fill: 512 x 16B chunks, 1 per thread
    const __half* aptr; unsigned asz; unsigned aoff;
    {
        int r = tid >> 2, k8 = (tid & 3) * 8;
        int m = m0 + r;
        int ok = m < cnt;
        int tok = ok ? g_rowtok[e * CC + m] : 0;
        aptr = g_xh + (size_t)tok * HH + k8;
        asz  = ok ? 16u : 0u;
        aoff = (unsigned)(r * 40 + k8) * 2u;
    }
    // B fill: 1024 chunks, 2 per thread
    const __half* bptr[2]; unsigned boff[2];
    #pragma unroll
    for (int i = 0; i < 2; i++) {
        int c = tid + i * 512;
        int r = c >> 2, k8 = (c & 3) * 8;
        const __half* base = (r < 128)
            ? g_wgh + ((size_t)e * II + n0 + r) * HH
            : g_wuh + ((size_t)e * II + n0 + (r - 128)) * HH;
        bptr[i] = base + k8;
        boff[i] = (unsigned)(G1_AB + (r * 40 + k8) * 2);
    }

    int warp = tid >> 5, lane = tid & 31;
    int wm = (warp & 3) * 32, wn = (warp >> 2) * 32;
    int gq = lane >> 2, t = lane & 3;

    unsigned a_lane = (unsigned)(((lane & 15) * 40 + (lane >> 4) * 8) * 2);
    unsigned b_lane = (unsigned)(((((lane & 7) + ((lane >> 4) & 1) * 8)) * 40
                                  + ((lane >> 3) & 1) * 8) * 2);

    float acc[2][2][4][4] = {};   // [kind][im][nt][c]

    #pragma unroll
    for (int s = 0; s < 2; s++) {
        int k0 = s * 32;
        unsigned so = sbase + s * G1_STG;
        cpa(so + aoff, aptr + k0, asz);
        #pragma unroll
        for (int i = 0; i < 2; i++) cpa(so + boff[i], bptr[i] + k0, 16);
        CP_COMMIT;
    }

    const int NK = HH / 32;
    int s = 0;
    for (int kt = 0; kt < NK; kt++) {
        CP_WAIT1;
        __syncthreads();
        if (kt + 2 < NK) {
            int k0 = (kt + 2) * 32;
            int s2 = s + 2; if (s2 >= 3) s2 -= 3;
            unsigned so = sbase + s2 * G1_STG;
            cpa(so + aoff, aptr + k0, asz);
            #pragma unroll
            for (int i = 0; i < 2; i++) cpa(so + boff[i], bptr[i] + k0, 16);
        }
        CP_COMMIT;

        unsigned sA = sbase + s * G1_STG;
        unsigned sB = sA + G1_AB;
        #pragma unroll
        for (int ks = 0; ks < 2; ks++) {
            unsigned a[2][4];
            #pragma unroll
            for (int im = 0; im < 2; im++)
                ldsm4(a[im][0], a[im][1], a[im][2], a[im][3],
                      sA + a_lane + (unsigned)((wm + im * 16) * 80 + ks * 32));
            #pragma unroll
            for (int kind = 0; kind < 2; kind++) {
                #pragma unroll
                for (int ntp = 0; ntp < 2; ntp++) {
                    unsigned b0, b1, b2, b3;
                    ldsm4(b0, b1, b2, b3,
                          sB + b_lane + (unsigned)((kind * 128 + wn + ntp * 16) * 80 + ks * 32));
                    #pragma unroll
                    for (int im = 0; im < 2; im++) {
                        mma16(acc[kind][im][2 * ntp],     a[im], b0, b1);
                        mma16(acc[kind][im][2 * ntp + 1], a[im], b2, b3);
                    }
                }
            }
        }
        if (++s >= 3) s -= 3;
    }

    #pragma unroll
    for (int im = 0; im < 2; im++) {
        #pragma unroll
        for (int h2 = 0; h2 < 2; h2++) {
            int m = m0 + wm + im * 16 + gq + h2 * 8;
            if (m < cnt) {
                __half* dst = g_h + ((size_t)e * CC + m) * II + n0 + wn + 2 * t;
                #pragma unroll
                for (int nt = 0; nt < 4; nt++) {
                    float g0 = acc[0][im][nt][h2 * 2],     g1 = acc[0][im][nt][h2 * 2 + 1];
                    float u0 = acc[1][im][nt][h2 * 2],     u1 = acc[1][im][nt][h2 * 2 + 1];
                    float r0 = g0 * (1.f / (1.f + expf(-g0))) * u0;
                    float r1 = g1 * (1.f / (1.f + expf(-g1))) * u1;
                    *(__half2*)(dst + nt * 8) = __floats2half2_rn(r0, r1);
                }
            }
        }
    }
}

// ---------------------------------------------------------------------------
// GEMM2: 512 threads, 16 warps (4m x 4n), warp tile 32m x 64n.
// BM=128, BN=256, BK=32, 3-stage cp.async -> g_y fp16.
// ---------------------------------------------------------------------------
#define G2_AB   (128 * 40 * 2)
#define G2_BB   (256 * 40 * 2)
#define G2_STG  (G2_AB + G2_BB)

__global__ __launch_bounds__(512, 1) void gemm2_kernel()
{
    extern __shared__ char smem[];
    int e   = blockIdx.z;
    int cnt = min(g_cnt[e], CC);
    int m0  = blockIdx.y * 128;
    if (m0 >= cnt) return;
    int n0  = blockIdx.x * 256;

    int tid = threadIdx.x;
    unsigned sbase = (unsigned)__cvta_generic_to_shared(smem);

    const __half* aptr; unsigned aoff;
    {
        int r = tid >> 2, k8 = (tid & 3) * 8;
        aptr = g_h + ((size_t)e * CC + m0 + r) * II + k8;  // stale rows masked in epilogue
        aoff = (unsigned)(r * 40 + k8) * 2u;
    }
    const __half* bptr[2]; unsigned boff[2];
    #pragma unroll
    for (int i = 0; i < 2; i++) {
        int c = tid + i * 512;
        int r = c >> 2, k8 = (c & 3) * 8;
        bptr[i] = g_wdh + ((size_t)e * HH + n0 + r) * II + k8;
        boff[i] = (unsigned)(G2_AB + (r * 40 + k8) * 2);
    }

    int warp = tid >> 5, lane = tid & 31;
    int wm = (warp & 3) * 32, wn = (warp >> 2) * 64;
    int gq = lane >> 2, t = lane & 3;

    unsigned a_lane = (unsigned)(((lane & 15) * 40 + (lane >> 4) * 8) * 2);
    unsigned b_lane = (unsigned)(((((lane & 7) + ((lane >> 4) & 1) * 8)) * 40
                                  + ((lane >> 3) & 1) * 8) * 2);

    float acc[2][8][4] = {};   // [im][nt][c]

    #pragma unroll
    for (int s = 0; s < 2; s++) {
        int k0 = s * 32;
        unsigned so = sbase + s * G2_STG;
        cpa(so + aoff, aptr + k0, 16);
        #pragma unroll
        for (int i = 0; i < 2; i++) cpa(so + boff[i], bptr[i] + k0, 16);
        CP_COMMIT;
    }

    const int NK = II / 32;
    int s = 0;
    for (int kt = 0; kt < NK; kt++) {
        CP_WAIT1;
        __syncthreads();
        if (kt + 2 < NK) {
            int k0 = (kt + 2) * 32;
            int s2 = s + 2; if (s2 >= 3) s2 -= 3;
            unsigned so = sbase + s2 * G2_STG;
            cpa(so + aoff, aptr + k0, 16);
            #pragma unroll
            for (int i = 0; i < 2; i++) cpa(so + boff[i], bptr[i] + k0, 16);
        }
        CP_COMMIT;

        unsigned sA = sbase + s * G2_STG;
        unsigned sB = sA + G2_AB;
        #pragma unroll
        for (int ks = 0; ks < 2; ks++) {
            unsigned a[2][4];
            #pragma unroll
            for (int im = 0; im < 2; im++)
                ldsm4(a[im][0], a[im][1], a[im][2], a[im][3],
                      sA + a_lane + (unsigned)((wm + im * 16) * 80 + ks * 32));
            #pragma unroll
            for (int ntp = 0; ntp < 4; ntp++) {
                unsigned b0, b1, b2, b3;
                ldsm4(b0, b1, b2, b3,
                      sB + b_lane + (unsigned)((wn + ntp * 16) * 80 + ks * 32));
                #pragma unroll
                for (int im = 0; im < 2; im++) {
                    mma16(acc[im][2 * ntp],     a[im], b0, b1);
                    mma16(acc[im][2 * ntp + 1], a[im], b2, b3);
                }
            }
        }
        if (++s >= 3) s -= 3;
    }

    #pragma unroll
    for (int im = 0; im < 2; im++) {
        #pragma unroll
        for (int h2 = 0; h2 < 2; h2++) {
            int m = m0 + wm + im * 16 + gq + h2 * 8;
            if (m < cnt) {
                __half* dst = g_y + ((size_t)e * CC + m) * HH + n0 + wn + 2 * t;
                #pragma unroll
                for (int nt = 0; nt < 8; nt++)
                    *(__half2*)(dst + nt * 8) =
                        __floats2half2_rn(acc[im][nt][h2 * 2], acc[im][nt][h2 * 2 + 1]);
            }
        }
    }
}

// ---------------------------------------------------------------------------
// Combine: out[tok] = sum_k w[k] * g_y[e_k, pos_k]  (block per token)
// ---------------------------------------------------------------------------
__global__ __launch_bounds__(128) void combine_kernel(float* __restrict__ out)
{
    int tok = blockIdx.x;
    int tid = threadIdx.x;

    __shared__ const __half* srow[KK];
    __shared__ float swk[KK];
    if (tid < KK) {
        int e = g_te[tok * KK + tid];
        int p = g_tpos[tok * KK + tid];
        srow[tid] = (p < CC) ? (g_y + ((size_t)e * CC + p) * HH) : (const __half*)0;
        swk[tid]  = g_tw[tok * KK + tid];
    }
    __syncthreads();

    const __half* r[KK]; float w[KK];
    #pragma unroll
    for (int k = 0; k < KK; k++) { r[k] = srow[k]; w[k] = swk[k]; }

    #pragma unroll
    for (int j = 0; j < HH / 2 / 128; j++) {
        int c = tid + j * 128;
        float2 acc = make_float2(0.f, 0.f);
        #pragma unroll
        for (int k = 0; k < KK; k++) {
            if (r[k]) {
                __half2 hv = *(const __half2*)(r[k] + 2 * c);
                float2 v = __half22float2(hv);
                acc.x = fmaf(w[k], v.x, acc.x);
                acc.y = fmaf(w[k], v.y, acc.y);
            }
        }
        *(float2*)(out + (size_t)tok * HH + 2 * c) = acc;
    }
}

// ---------------------------------------------------------------------------
extern "C" void kernel_launch(void* const* d_in, const int* in_sizes, int n_in,
                              void* d_out, int out_size)
{
    const float* x      = (const float*)d_in[0];
    const float* gw     = (const float*)d_in[1];
    const float* bias   = (const float*)d_in[2];
    const float* w_gate = (const float*)d_in[3];
    const float* w_up   = (const float*)d_in[4];
    const float* w_down = (const float*)d_in[5];
    float* out = (float*)d_out;

    cudaFuncSetAttribute(gemm1_kernel, cudaFuncAttributeMaxDynamicSharedMemorySize, 3 * G1_STG);
    cudaFuncSetAttribute(gemm2_kernel, cudaFuncAttributeMaxDynamicSharedMemorySize, 3 * G2_STG);

    k1_kernel<<<64 + NC1, 256>>>(x, gw, (const float4*)w_gate, (const float4*)w_up);
    topk_kernel<<<TT / 16, 512>>>(bias);
    gemm1_kernel<<<dim3(II / 128, CC / 128, EE + 4), 512, 3 * G1_STG>>>((const float4*)w_down);
    gemm2_kernel<<<dim3(HH / 256, CC / 128, EE), 512, 3 * G2_STG>>>();
    combine_kernel<<<TT, 128>>>(out);
}